// round 4
// baseline (speedup 1.0000x reference)
#include <cuda_runtime.h>
#include <cuda_bf16.h>
#include <cstdint>
#include <cstddef>

// ---------------------------------------------------------------------------
// ChannelAttention: B=4, D=8, H=32, W=32, C=512, 8 heads x head_dim 64
//   split x,W once -> bf16 hi/lo;  GEMMs = cp.async + ldmatrix + bf16x3 mma
// ---------------------------------------------------------------------------

static constexpr int kBatch    = 4;
static constexpr int kTok      = 8192;
static constexpr int kC        = 512;
static constexpr int kHD       = 64;
static constexpr int kM        = kBatch * kTok;     // 32768
static constexpr int kQKVld    = 3 * kC;            // 1536
static constexpr int kBH       = kBatch * 8;        // 32
static constexpr int kChunks   = 16;
static constexpr int kChunkTok = kTok / kChunks;    // 512
static constexpr float kScale  = 0.125f;

// Scratch (device globals; fully rewritten each launch -> graph-safe)
__device__ float g_qkv [(size_t)kM * kQKVld];
__device__ float g_part[(size_t)kBH * kChunks * kHD * kHD];
__device__ float g_attn[(size_t)kBH * kHD * kHD];
__device__ float g_outa[(size_t)kM * kC];

__device__ __nv_bfloat16 g_x_hi [(size_t)kM * kC];
__device__ __nv_bfloat16 g_x_lo [(size_t)kM * kC];
__device__ __nv_bfloat16 g_wq_hi[(size_t)kQKVld * kC];
__device__ __nv_bfloat16 g_wq_lo[(size_t)kQKVld * kC];
__device__ __nv_bfloat16 g_wp_hi[(size_t)kC * kC];
__device__ __nv_bfloat16 g_wp_lo[(size_t)kC * kC];
__device__ __nv_bfloat16 g_oa_hi[(size_t)kM * kC];
__device__ __nv_bfloat16 g_oa_lo[(size_t)kM * kC];

// ---------------------------------------------------------------------------
// fp32 -> (hi, lo) bf16 split, vectorized (4 floats / thread)
// ---------------------------------------------------------------------------
__global__ __launch_bounds__(256) void split_f32(
    const float* __restrict__ src,
    __nv_bfloat16* __restrict__ hi, __nv_bfloat16* __restrict__ lo, int n4)
{
    int i = blockIdx.x * blockDim.x + threadIdx.x;
    if (i >= n4) return;
    float4 f = ((const float4*)src)[i];
    float a[4] = {f.x, f.y, f.z, f.w};
    __nv_bfloat16 h[4], l[4];
#pragma unroll
    for (int j = 0; j < 4; j++) {
        h[j] = __float2bfloat16_rn(a[j]);
        l[j] = __float2bfloat16_rn(a[j] - __bfloat162float(h[j]));
    }
    ((uint2*)hi)[i] = *(uint2*)h;
    ((uint2*)lo)[i] = *(uint2*)l;
}

// ---------------------------------------------------------------------------
// mma / ldmatrix / cp.async primitives
// ---------------------------------------------------------------------------
__device__ __forceinline__ void ldsm_x4(uint32_t addr, uint32_t* r)
{
    asm volatile("ldmatrix.sync.aligned.m8n8.x4.shared.b16 {%0,%1,%2,%3}, [%4];\n"
                 : "=r"(r[0]), "=r"(r[1]), "=r"(r[2]), "=r"(r[3])
                 : "r"(addr));
}

__device__ __forceinline__ void mma16816(float* c, const uint32_t* a,
                                         uint32_t b0, uint32_t b1)
{
    asm volatile(
        "mma.sync.aligned.m16n8k16.row.col.f32.bf16.bf16.f32 "
        "{%0,%1,%2,%3}, {%4,%5,%6,%7}, {%8,%9}, {%0,%1,%2,%3};\n"
        : "+f"(c[0]), "+f"(c[1]), "+f"(c[2]), "+f"(c[3])
        : "r"(a[0]), "r"(a[1]), "r"(a[2]), "r"(a[3]), "r"(b0), "r"(b1));
}

__device__ __forceinline__ void cp16(uint32_t dst, const void* src)
{
    asm volatile("cp.async.cg.shared.global [%0], [%1], 16;\n"
                 :: "r"(dst), "l"(src));
}
__device__ __forceinline__ void cp_commit()
{
    asm volatile("cp.async.commit_group;\n");
}
template <int N> __device__ __forceinline__ void cp_wait()
{
    asm volatile("cp.async.wait_group %0;\n" :: "n"(N));
}

// ---------------------------------------------------------------------------
// C = A @ B^T (+bias), inputs pre-split bf16 hi/lo, row-major with row len K.
// Block 128x128, BK=16, 256 threads (8 warps of 32x64), 2-stage cp.async.
// ---------------------------------------------------------------------------
static constexpr int kPad = 24;  // bf16 row stride (48 B) -> conflict-free ldsm

__global__ __launch_bounds__(256) void gemm_tc2(
    const __nv_bfloat16* __restrict__ Ahi, const __nv_bfloat16* __restrict__ Alo,
    const __nv_bfloat16* __restrict__ Bhi, const __nv_bfloat16* __restrict__ Blo,
    const float* __restrict__ bias,
    float* __restrict__ C, int ldc, int K)
{
    __shared__ __align__(16) __nv_bfloat16 sA[2][2][128][kPad];
    __shared__ __align__(16) __nv_bfloat16 sB[2][2][128][kPad];

    const int tid  = threadIdx.x;
    const int wid  = tid >> 5;
    const int lane = tid & 31;
    const int m0 = blockIdx.y * 128;
    const int n0 = blockIdx.x * 128;
    const int wm = (wid >> 1) * 32;
    const int wn = (wid & 1) * 64;

    // cp.async mapping: one 16B chunk per (matrix, precision) per thread
    const int grow = tid >> 1;        // 0..127
    const int gk8  = (tid & 1) * 8;   // 0 or 8
    const __nv_bfloat16* gAh = Ahi + (size_t)(m0 + grow) * K + gk8;
    const __nv_bfloat16* gAl = Alo + (size_t)(m0 + grow) * K + gk8;
    const __nv_bfloat16* gBh = Bhi + (size_t)(n0 + grow) * K + gk8;
    const __nv_bfloat16* gBl = Blo + (size_t)(n0 + grow) * K + gk8;

    const uint32_t dAh[2] = {
        (uint32_t)__cvta_generic_to_shared(&sA[0][0][grow][gk8]),
        (uint32_t)__cvta_generic_to_shared(&sA[1][0][grow][gk8])};
    const uint32_t dAl[2] = {
        (uint32_t)__cvta_generic_to_shared(&sA[0][1][grow][gk8]),
        (uint32_t)__cvta_generic_to_shared(&sA[1][1][grow][gk8])};
    const uint32_t dBh[2] = {
        (uint32_t)__cvta_generic_to_shared(&sB[0][0][grow][gk8]),
        (uint32_t)__cvta_generic_to_shared(&sB[1][0][grow][gk8])};
    const uint32_t dBl[2] = {
        (uint32_t)__cvta_generic_to_shared(&sB[0][1][grow][gk8]),
        (uint32_t)__cvta_generic_to_shared(&sB[1][1][grow][gk8])};

    auto issue = [&](int s, int kt) {
        const int off = kt * 16;
        cp16(dAh[s], gAh + off);
        cp16(dAl[s], gAl + off);
        cp16(dBh[s], gBh + off);
        cp16(dBl[s], gBl + off);
        cp_commit();
    };

    // ldmatrix per-lane mapping (validated in round 3)
    const int aRow = lane & 15;
    const int aKof = (lane >> 4) * 8;
    const int bRow = (lane & 7) + ((lane >> 4) & 1) * 8;
    const int bKof = ((lane >> 3) & 1) * 8;

    float acc[2][8][4];
#pragma unroll
    for (int mt = 0; mt < 2; mt++)
#pragma unroll
        for (int nt = 0; nt < 8; nt++)
#pragma unroll
            for (int i = 0; i < 4; i++)
                acc[mt][nt][i] = 0.f;

    const int NK = K / 16;
    issue(0, 0);
    issue(1, 1);

#pragma unroll 1
    for (int kt = 0; kt < NK; kt++) {
        const int cur = kt & 1;
        cp_wait<1>();
        __syncthreads();

        // load all fragments for this k-tile into registers
        uint32_t ahi[2][4], alo[2][4], bhi[4][4], blo[4][4];
#pragma unroll
        for (int mt = 0; mt < 2; mt++) {
            ldsm_x4((uint32_t)__cvta_generic_to_shared(
                        &sA[cur][0][wm + mt * 16 + aRow][aKof]), ahi[mt]);
            ldsm_x4((uint32_t)__cvta_generic_to_shared(
                        &sA[cur][1][wm + mt * 16 + aRow][aKof]), alo[mt]);
        }
#pragma unroll
        for (int ng = 0; ng < 4; ng++) {
            ldsm_x4((uint32_t)__cvta_generic_to_shared(
                        &sB[cur][0][wn + ng * 16 + bRow][bKof]), bhi[ng]);
            ldsm_x4((uint32_t)__cvta_generic_to_shared(
                        &sB[cur][1][wn + ng * 16 + bRow][bKof]), blo[ng]);
        }
        __syncthreads();   // frags in regs; buffer reusable

        if (kt + 2 < NK) issue(cur, kt + 2);
        else             cp_commit();   // keep group count aligned

        // 48 MMAs from registers (overlaps the cp.async just issued)
#pragma unroll
        for (int ng = 0; ng < 4; ng++) {
#pragma unroll
            for (int mt = 0; mt < 2; mt++) {
#pragma unroll
                for (int j = 0; j < 2; j++) {
                    float* c = acc[mt][ng * 2 + j];
                    mma16816(c, ahi[mt], bhi[ng][2 * j], bhi[ng][2 * j + 1]);
                    mma16816(c, ahi[mt], blo[ng][2 * j], blo[ng][2 * j + 1]);
                    mma16816(c, alo[mt], bhi[ng][2 * j], bhi[ng][2 * j + 1]);
                }
            }
        }
    }

    // epilogue
    const int g  = lane >> 2;
    const int tg = lane & 3;
#pragma unroll
    for (int mt = 0; mt < 2; mt++) {
#pragma unroll
        for (int nt = 0; nt < 8; nt++) {
            const int r   = m0 + wm + mt * 16 + g;
            const int col = n0 + wn + nt * 8 + tg * 2;
            float b0 = bias ? bias[col]     : 0.f;
            float b1 = bias ? bias[col + 1] : 0.f;
            float2 o0, o1;
            o0.x = acc[mt][nt][0] + b0; o0.y = acc[mt][nt][1] + b1;
            o1.x = acc[mt][nt][2] + b0; o1.y = acc[mt][nt][3] + b1;
            *(float2*)(C + (size_t)r * ldc + col)       = o0;
            *(float2*)(C + (size_t)(r + 8) * ldc + col) = o1;
        }
    }
}

// ---------------------------------------------------------------------------
// Partial K^T V: grid (chunk, bh). 512 tokens -> 64x64 partial (un-scaled).
// ---------------------------------------------------------------------------
__global__ __launch_bounds__(256) void ktv_partial(
    const float* __restrict__ qkv, float* __restrict__ part)
{
    const int chunk = blockIdx.x;
    const int bh    = blockIdx.y;
    const int b = bh >> 3, h = bh & 7;

    __shared__ float ks[16][64];
    __shared__ float vs[16][64];

    const int tid = threadIdx.x;
    const int ty = tid >> 4;
    const int tx = tid & 15;
    const int lRow = tid >> 4;
    const int lCol = (tid & 15) * 4;

    const float* base  = qkv + (size_t)(b * kTok + chunk * kChunkTok) * kQKVld + h * kHD;
    const float* kbase = base + kC;
    const float* vbase = base + 2 * kC;

    float acc[4][4];
#pragma unroll
    for (int i = 0; i < 4; i++)
#pragma unroll
        for (int j = 0; j < 4; j++)
            acc[i][j] = 0.f;

    for (int t0 = 0; t0 < kChunkTok; t0 += 16) {
        float4 kv = *(const float4*)(kbase + (size_t)(t0 + lRow) * kQKVld + lCol);
        float4 vv = *(const float4*)(vbase + (size_t)(t0 + lRow) * kQKVld + lCol);
        __syncthreads();
        *(float4*)&ks[lRow][lCol] = kv;
        *(float4*)&vs[lRow][lCol] = vv;
        __syncthreads();

#pragma unroll
        for (int kk = 0; kk < 16; kk++) {
            float4 ka = *(const float4*)&ks[kk][ty * 4];
            float4 va = *(const float4*)&vs[kk][tx * 4];
            float a[4] = {ka.x, ka.y, ka.z, ka.w};
            float v[4] = {va.x, va.y, va.z, va.w};
#pragma unroll
            for (int i = 0; i < 4; i++)
#pragma unroll
                for (int j = 0; j < 4; j++)
                    acc[i][j] += a[i] * v[j];
        }
    }

    float* p = part + ((size_t)(bh * kChunks + chunk)) * kHD * kHD;
#pragma unroll
    for (int i = 0; i < 4; i++) {
        float4 o;
        o.x = acc[i][0]; o.y = acc[i][1]; o.z = acc[i][2]; o.w = acc[i][3];
        *(float4*)(p + (ty * 4 + i) * kHD + tx * 4) = o;
    }
}

// ---------------------------------------------------------------------------
__global__ __launch_bounds__(256) void softmax_attn(
    const float* __restrict__ part, float* __restrict__ attn)
{
    const int bh   = blockIdx.x;
    const int warp = threadIdx.x >> 5;
    const int lane = threadIdx.x & 31;

    for (int r = 0; r < 8; r++) {
        const int d = warp * 8 + r;
        float v1 = 0.f, v2 = 0.f;
        for (int c = 0; c < kChunks; c++) {
            const float* row = part + ((size_t)(bh * kChunks + c) * kHD + d) * kHD;
            v1 += row[lane];
            v2 += row[lane + 32];
        }
        v1 *= kScale; v2 *= kScale;
        float m = fmaxf(v1, v2);
#pragma unroll
        for (int s = 16; s > 0; s >>= 1)
            m = fmaxf(m, __shfl_xor_sync(0xffffffffu, m, s));
        float e1 = expf(v1 - m);
        float e2 = expf(v2 - m);
        float sm = e1 + e2;
#pragma unroll
        for (int s = 16; s > 0; s >>= 1)
            sm += __shfl_xor_sync(0xffffffffu, sm, s);
        float inv = 1.f / sm;
        float* arow = attn + ((size_t)bh * kHD + d) * kHD;
        arow[lane]      = e1 * inv;
        arow[lane + 32] = e2 * inv;
    }
}

// ---------------------------------------------------------------------------
__global__ __launch_bounds__(256) void q_attn(
    const float* __restrict__ qkv, const float* __restrict__ attn,
    float* __restrict__ outa)
{
    const int mt = blockIdx.x;
    const int bh = blockIdx.y;
    const int b = bh >> 3, h = bh & 7;

    __shared__ float at[64][68];
    __shared__ float qs[16][128];

    const int tid = threadIdx.x;
    const int ty = tid >> 4;
    const int tx = tid & 15;

    const float* ag = attn + (size_t)bh * kHD * kHD;
    for (int i = tid; i < kHD * kHD; i += 256) {
        int d = i >> 6, e = i & 63;
        at[e][d] = ag[i];
    }

    const int lRow = tid >> 1;
    const int lK   = (tid & 1) * 8;
    const float* qbase = qkv + ((size_t)(b * kTok + mt * 128 + lRow)) * kQKVld
                             + h * kHD + lK;

    float acc[8][4];
#pragma unroll
    for (int i = 0; i < 8; i++)
#pragma unroll
        for (int j = 0; j < 4; j++)
            acc[i][j] = 0.f;

    for (int e0 = 0; e0 < kHD; e0 += 16) {
        float4 q0 = *(const float4*)(qbase + e0);
        float4 q1 = *(const float4*)(qbase + e0 + 4);
        __syncthreads();
        qs[lK+0][lRow] = q0.x; qs[lK+1][lRow] = q0.y;
        qs[lK+2][lRow] = q0.z; qs[lK+3][lRow] = q0.w;
        qs[lK+4][lRow] = q1.x; qs[lK+5][lRow] = q1.y;
        qs[lK+6][lRow] = q1.z; qs[lK+7][lRow] = q1.w;
        __syncthreads();

#pragma unroll
        for (int kk = 0; kk < 16; kk++) {
            const int e = e0 + kk;
            float4 a0 = *(const float4*)&qs[kk][ty * 8];
            float4 a1 = *(const float4*)&qs[kk][ty * 8 + 4];
            float4 bv = *(const float4*)&at[e][tx * 4];
            float a[8] = {a0.x, a0.y, a0.z, a0.w, a1.x, a1.y, a1.z, a1.w};
            float bb[4] = {bv.x, bv.y, bv.z, bv.w};
#pragma unroll
            for (int i = 0; i < 8; i++)
#pragma unroll
                for (int j = 0; j < 4; j++)
                    acc[i][j] += a[i] * bb[j];
        }
    }

#pragma unroll
    for (int i = 0; i < 8; i++) {
        const int m = mt * 128 + ty * 8 + i;
        float4 o;
        o.x = acc[i][0]; o.y = acc[i][1]; o.z = acc[i][2]; o.w = acc[i][3];
        *(float4*)(outa + ((size_t)(b * kTok + m)) * kC + h * kHD + tx * 4) = o;
    }
}

// ---------------------------------------------------------------------------
extern "C" void kernel_launch(void* const* d_in, const int* in_sizes, int n_in,
                              void* d_out, int out_size)
{
    const float* x     = (const float*)d_in[0];
    const float* Wqkv  = (const float*)d_in[1];
    const float* Wproj = (const float*)d_in[2];
    const float* bproj = (const float*)d_in[3];
    float* out = (float*)d_out;

    float *qkv, *part, *attn, *outa;
    cudaGetSymbolAddress((void**)&qkv,  g_qkv);
    cudaGetSymbolAddress((void**)&part, g_part);
    cudaGetSymbolAddress((void**)&attn, g_attn);
    cudaGetSymbolAddress((void**)&outa, g_outa);

    __nv_bfloat16 *xh, *xl, *wqh, *wql, *wph, *wpl, *oah, *oal;
    cudaGetSymbolAddress((void**)&xh,  g_x_hi);
    cudaGetSymbolAddress((void**)&xl,  g_x_lo);
    cudaGetSymbolAddress((void**)&wqh, g_wq_hi);
    cudaGetSymbolAddress((void**)&wql, g_wq_lo);
    cudaGetSymbolAddress((void**)&wph, g_wp_hi);
    cudaGetSymbolAddress((void**)&wpl, g_wp_lo);
    cudaGetSymbolAddress((void**)&oah, g_oa_hi);
    cudaGetSymbolAddress((void**)&oal, g_oa_lo);

    // 0) one-time-per-launch splits (memory bound)
    {
        int n4 = kM * kC / 4;
        split_f32<<<(n4 + 255) / 256, 256>>>(x, xh, xl, n4);
        n4 = kQKVld * kC / 4;
        split_f32<<<(n4 + 255) / 256, 256>>>(Wqkv, wqh, wql, n4);
        n4 = kC * kC / 4;
        split_f32<<<(n4 + 255) / 256, 256>>>(Wproj, wph, wpl, n4);
    }

    // 1) qkv = x @ Wqkv^T   (32768 x 1536, K=512)
    gemm_tc2<<<dim3(kQKVld / 128, kM / 128), 256>>>(
        xh, xl, wqh, wql, nullptr, qkv, kQKVld, kC);

    // 2) partial K^T V over 16 token chunks
    ktv_partial<<<dim3(kChunks, kBH), 256>>>(qkv, part);

    // 3) reduce + scale + softmax
    softmax_attn<<<kBH, 256>>>(part, attn);

    // 4) out_h = Q @ attn^T
    q_attn<<<dim3(kTok / 128, kBH), 256>>>(qkv, attn, outa);

    // 4b) split outa for GEMM2
    {
        int n4 = kM * kC / 4;
        split_f32<<<(n4 + 255) / 256, 256>>>(outa, oah, oal, n4);
    }

    // 5) y = out @ Wproj^T + bproj   (32768 x 512, K=512)
    gemm_tc2<<<dim3(kC / 128, kM / 128), 256>>>(
        oah, oal, wph, wpl, bproj, out, kC, kC);
}

// round 6
// speedup vs baseline: 1.6760x; 1.6760x over previous
#include <cuda_runtime.h>
#include <cuda_bf16.h>
#include <cstdint>
#include <cstddef>

// ---------------------------------------------------------------------------
// ChannelAttention via Gram factorization:
//   G_b   = X_b^T X_b                       (bf16x3 mma.sync, ldmatrix.trans)
//   P1    = Wk @ G_b          (FFMA, G symmetric so A@B^T works)
//   logit = SCALE * P1_h @ Wv_h^T, softmax  (FFMA, per b,h)
//   Wht   = (attn_h @ Wq_h)^T  per batch    (FFMA)
//   Wt_b  = Wproj @ Wht_b^T?  -> gemm_abT(Wproj, Wht)   (FFMA)
//   y     = X @ Wt_b^T + bproj              (bf16x3 mma.sync)
// ---------------------------------------------------------------------------

static constexpr int   kTok   = 8192;
static constexpr int   kC     = 512;
static constexpr int   kM     = 4 * kTok;       // 32768
static constexpr float kScale = 0.125f;
static constexpr int   kSplitK = 4;             // gram split-K
static constexpr int   kKS     = kTok / kSplitK;  // 2048 tokens per split

// Scratch (device globals; all read locations rewritten each launch)
__device__ __nv_bfloat16 g_xh [(size_t)kM * kC];
__device__ __nv_bfloat16 g_xl [(size_t)kM * kC];
__device__ float g_gpart[(size_t)kSplitK * 4 * kC * kC];   // 16 MB (upper blocks only)
__device__ float g_G    [(size_t)4 * kC * kC];
__device__ float g_P1   [(size_t)4 * kC * kC];
__device__ float g_attn [(size_t)32 * 64 * 64];
__device__ float g_wht  [(size_t)4 * kC * kC];             // What^T per batch
__device__ float g_wt   [(size_t)4 * kC * kC];             // Wtilde per batch
__device__ __nv_bfloat16 g_wth[(size_t)4 * kC * kC];
__device__ __nv_bfloat16 g_wtl[(size_t)4 * kC * kC];

// ---------------------------------------------------------------------------
// primitives
// ---------------------------------------------------------------------------
__device__ __forceinline__ void ldsm_x4(uint32_t addr, uint32_t* r)
{
    asm volatile("ldmatrix.sync.aligned.m8n8.x4.shared.b16 {%0,%1,%2,%3}, [%4];\n"
                 : "=r"(r[0]), "=r"(r[1]), "=r"(r[2]), "=r"(r[3]) : "r"(addr));
}
__device__ __forceinline__ void ldsm_x4_t(uint32_t addr, uint32_t* r)
{
    asm volatile("ldmatrix.sync.aligned.m8n8.x4.trans.shared.b16 {%0,%1,%2,%3}, [%4];\n"
                 : "=r"(r[0]), "=r"(r[1]), "=r"(r[2]), "=r"(r[3]) : "r"(addr));
}
__device__ __forceinline__ void mma16816(float* c, const uint32_t* a,
                                         uint32_t b0, uint32_t b1)
{
    asm volatile(
        "mma.sync.aligned.m16n8k16.row.col.f32.bf16.bf16.f32 "
        "{%0,%1,%2,%3}, {%4,%5,%6,%7}, {%8,%9}, {%0,%1,%2,%3};\n"
        : "+f"(c[0]), "+f"(c[1]), "+f"(c[2]), "+f"(c[3])
        : "r"(a[0]), "r"(a[1]), "r"(a[2]), "r"(a[3]), "r"(b0), "r"(b1));
}
__device__ __forceinline__ void cp16(uint32_t dst, const void* src)
{
    asm volatile("cp.async.cg.shared.global [%0], [%1], 16;\n" :: "r"(dst), "l"(src));
}
__device__ __forceinline__ void cp_commit()
{
    asm volatile("cp.async.commit_group;\n");
}
template <int N> __device__ __forceinline__ void cp_wait()
{
    asm volatile("cp.async.wait_group %0;\n" :: "n"(N));
}

// ---------------------------------------------------------------------------
// fp32 -> (hi, lo) bf16 split
// ---------------------------------------------------------------------------
__global__ __launch_bounds__(256) void split_f32(
    const float* __restrict__ src,
    __nv_bfloat16* __restrict__ hi, __nv_bfloat16* __restrict__ lo, int n4)
{
    int i = blockIdx.x * blockDim.x + threadIdx.x;
    if (i >= n4) return;
    float4 f = ((const float4*)src)[i];
    float a[4] = {f.x, f.y, f.z, f.w};
    __nv_bfloat16 h[4], l[4];
#pragma unroll
    for (int j = 0; j < 4; j++) {
        h[j] = __float2bfloat16_rn(a[j]);
        l[j] = __float2bfloat16_rn(a[j] - __bfloat162float(h[j]));
    }
    ((uint2*)hi)[i] = *(uint2*)h;
    ((uint2*)lo)[i] = *(uint2*)l;
}

// ---------------------------------------------------------------------------
// Gram partials: part[(s*4+b)] += X_b[s-chunk]^T X_b[s-chunk] for 128x128
// channel blocks with mblk <= nblk (upper triangle of 4x4 block grid).
// Token-major smem tiles, ldmatrix.trans fragments.
// Stage layout: Ah | Al | Bh | Bl, each 16 rows x 136 bf16 (272B rows).
// ---------------------------------------------------------------------------
static constexpr int kGramStage = 4 * 16 * 136 * 2;   // 17408 B
static constexpr int kGramSmem  = 3 * kGramStage;     // 52224 B

__global__ __launch_bounds__(256, 2) void gemm_gram(
    const __nv_bfloat16* __restrict__ Xhi,
    const __nv_bfloat16* __restrict__ Xlo,
    float* __restrict__ part)
{
    extern __shared__ __align__(16) char smem[];
    const uint32_t sbase = (uint32_t)__cvta_generic_to_shared(smem);

    // pair id -> (mblk, nblk) with mblk<=nblk
    int p = blockIdx.x, mb = 0;
    while (p >= 4 - mb) { p -= 4 - mb; mb++; }
    const int m0 = mb * 128, n0 = (mb + p) * 128;
    const int bz = blockIdx.y;           // b*4 + s
    const int b = bz >> 2, s = bz & 3;
    const size_t tokBase = (size_t)b * kTok + (size_t)s * kKS;

    const int tid = threadIdx.x, wid = tid >> 5, lane = tid & 31;
    const int wm = (wid >> 1) * 32, wn = (wid & 1) * 64;

    const int lrow = tid >> 4;          // 0..15 token row
    const int lch  = (tid & 15) * 8;    // channel offset (8 bf16 = 16B)

    auto issue = [&](int kt) {
        const uint32_t stg = sbase + (uint32_t)(kt % 3) * kGramStage;
        const size_t ro = (tokBase + (size_t)kt * 16 + lrow) * kC;
        const uint32_t d = (uint32_t)(lrow * 136 + lch) * 2;
        cp16(stg +          d, Xhi + ro + m0 + lch);
        cp16(stg + 4352u  + d, Xlo + ro + m0 + lch);
        cp16(stg + 8704u  + d, Xhi + ro + n0 + lch);
        cp16(stg + 13056u + d, Xlo + ro + n0 + lch);
        cp_commit();
    };

    // trans fragment lane mapping
    const int kA = (lane & 7) + ((lane >> 4) & 1) * 8;
    const int mA = ((lane >> 3) & 1) * 8;
    const int kB = (lane & 7) + ((lane >> 3) & 1) * 8;
    const int nB = ((lane >> 4) & 1) * 8;

    float acc[2][8][4];
#pragma unroll
    for (int mt = 0; mt < 2; mt++)
#pragma unroll
        for (int nt = 0; nt < 8; nt++)
#pragma unroll
            for (int i = 0; i < 4; i++) acc[mt][nt][i] = 0.f;

    const int NK = kKS / 16;   // 128
    issue(0); issue(1);

#pragma unroll 1
    for (int kt = 0; kt < NK; kt++) {
        cp_wait<1>();
        __syncthreads();
        if (kt + 2 < NK) issue(kt + 2);
        else             cp_commit();

        const uint32_t stg = sbase + (uint32_t)(kt % 3) * kGramStage;
        uint32_t ahi[2][4], alo[2][4];
#pragma unroll
        for (int mt = 0; mt < 2; mt++) {
            const uint32_t co = (uint32_t)(kA * 136 + wm + mt * 16 + mA) * 2;
            ldsm_x4_t(stg +         co, ahi[mt]);
            ldsm_x4_t(stg + 4352u + co, alo[mt]);
        }
#pragma unroll
        for (int ng = 0; ng < 4; ng++) {
            uint32_t bh[4], bl[4];
            const uint32_t co = (uint32_t)(kB * 136 + wn + ng * 16 + nB) * 2;
            ldsm_x4_t(stg + 8704u  + co, bh);
            ldsm_x4_t(stg + 13056u + co, bl);
#pragma unroll
            for (int mt = 0; mt < 2; mt++) {
#pragma unroll
                for (int j = 0; j < 2; j++) {
                    float* c = acc[mt][ng * 2 + j];
                    mma16816(c, ahi[mt], bh[2 * j], bh[2 * j + 1]);
                    mma16816(c, ahi[mt], bl[2 * j], bl[2 * j + 1]);
                    mma16816(c, alo[mt], bh[2 * j], bh[2 * j + 1]);
                }
            }
        }
    }

    const int g = lane >> 2, tg = lane & 3;
    float* P = part + (size_t)(s * 4 + b) * kC * kC;
#pragma unroll
    for (int mt = 0; mt < 2; mt++) {
#pragma unroll
        for (int nt = 0; nt < 8; nt++) {
            const int r   = m0 + wm + mt * 16 + g;
            const int col = n0 + wn + nt * 8 + tg * 2;
            *(float2*)(P + (size_t)r * kC + col) =
                make_float2(acc[mt][nt][0], acc[mt][nt][1]);
            *(float2*)(P + (size_t)(r + 8) * kC + col) =
                make_float2(acc[mt][nt][2], acc[mt][nt][3]);
        }
    }
}

// ---------------------------------------------------------------------------
// Reduce split-K partials with symmetric mirroring -> exactly symmetric G.
// ---------------------------------------------------------------------------
__global__ __launch_bounds__(256) void reduce_g(
    const float* __restrict__ part, float* __restrict__ G)
{
    const int i = blockIdx.x * 256 + threadIdx.x;   // 4*512*512 total
    const int b = i >> 18;
    const int r = (i >> 9) & 511;
    const int c = i & 511;
    const size_t src = ((r >> 7) <= (c >> 7))
        ? ((size_t)r * kC + c) : ((size_t)c * kC + r);
    float sum = 0.f;
#pragma unroll
    for (int s = 0; s < kSplitK; s++)
        sum += part[(size_t)(s * 4 + b) * kC * kC + src];
    G[(size_t)b * kC * kC + (size_t)r * kC + c] = sum;
}

// ---------------------------------------------------------------------------
// FFMA C = A @ B^T, batched over blockIdx.z with element strides.
// 128x128x16 tile, 256 threads, 8x8 per thread (round-1 validated).
// ---------------------------------------------------------------------------
__global__ __launch_bounds__(256) void gemm_abT_z(
    const float* __restrict__ A, int lda, size_t strideA,
    const float* __restrict__ B, int ldb, size_t strideB,
    float* __restrict__ C, int ldc, size_t strideC, int K)
{
    A += strideA * blockIdx.z;
    B += strideB * blockIdx.z;
    C += strideC * blockIdx.z;

    __shared__ float As[16][128];
    __shared__ float Bs[16][128];

    const int tid = threadIdx.x;
    const int m0  = blockIdx.y * 128;
    const int n0  = blockIdx.x * 128;
    const int ty  = tid >> 4;
    const int tx  = tid & 15;
    const int ldRow = tid >> 1;
    const int ldK   = (tid & 1) * 8;

    const float* Aptr = A + (size_t)(m0 + ldRow) * lda + ldK;
    const float* Bptr = B + (size_t)(n0 + ldRow) * ldb + ldK;

    float acc[8][8];
#pragma unroll
    for (int i = 0; i < 8; i++)
#pragma unroll
        for (int j = 0; j < 8; j++) acc[i][j] = 0.f;

    for (int k0 = 0; k0 < K; k0 += 16) {
        float4 a0 = *(const float4*)(Aptr + k0);
        float4 a1 = *(const float4*)(Aptr + k0 + 4);
        float4 b0 = *(const float4*)(Bptr + k0);
        float4 b1 = *(const float4*)(Bptr + k0 + 4);
        __syncthreads();
        As[ldK+0][ldRow]=a0.x; As[ldK+1][ldRow]=a0.y; As[ldK+2][ldRow]=a0.z; As[ldK+3][ldRow]=a0.w;
        As[ldK+4][ldRow]=a1.x; As[ldK+5][ldRow]=a1.y; As[ldK+6][ldRow]=a1.z; As[ldK+7][ldRow]=a1.w;
        Bs[ldK+0][ldRow]=b0.x; Bs[ldK+1][ldRow]=b0.y; Bs[ldK+2][ldRow]=b0.z; Bs[ldK+3][ldRow]=b0.w;
        Bs[ldK+4][ldRow]=b1.x; Bs[ldK+5][ldRow]=b1.y; Bs[ldK+6][ldRow]=b1.z; Bs[ldK+7][ldRow]=b1.w;
        __syncthreads();

#pragma unroll
        for (int kk = 0; kk < 16; kk++) {
            float4 ar0 = *(const float4*)&As[kk][ty * 8];
            float4 ar1 = *(const float4*)&As[kk][ty * 8 + 4];
            float4 br0 = *(const float4*)&Bs[kk][tx * 8];
            float4 br1 = *(const float4*)&Bs[kk][tx * 8 + 4];
            float a[8] = {ar0.x,ar0.y,ar0.z,ar0.w,ar1.x,ar1.y,ar1.z,ar1.w};
            float bb[8] = {br0.x,br0.y,br0.z,br0.w,br1.x,br1.y,br1.z,br1.w};
#pragma unroll
            for (int i = 0; i < 8; i++)
#pragma unroll
                for (int j = 0; j < 8; j++)
                    acc[i][j] += a[i] * bb[j];
        }
    }

#pragma unroll
    for (int i = 0; i < 8; i++) {
        float* crow = C + (size_t)(m0 + ty * 8 + i) * ldc + n0 + tx * 8;
        *(float4*)(crow)     = make_float4(acc[i][0],acc[i][1],acc[i][2],acc[i][3]);
        *(float4*)(crow + 4) = make_float4(acc[i][4],acc[i][5],acc[i][6],acc[i][7]);
    }
}

// ---------------------------------------------------------------------------
// logits_h = SCALE * P1_h @ Wv_h^T  (64x64, K=512), then row softmax -> attn.
// grid (head, batch), 256 threads.
// ---------------------------------------------------------------------------
__global__ __launch_bounds__(256) void logits_softmax(
    const float* __restrict__ P1, const float* __restrict__ Wqkv,
    float* __restrict__ attn)
{
    const int h = blockIdx.x, b = blockIdx.y;
    const float* p1 = P1 + (size_t)b * kC * kC + (size_t)(h * 64) * kC;
    const float* wv = Wqkv + (size_t)(1024 + h * 64) * kC;

    __shared__ float ps[16][68];
    __shared__ float vs[16][68];
    __shared__ float ls[64][68];

    const int tid = threadIdx.x;
    const int ty = tid >> 4, tx = tid & 15;
    const int lr = tid >> 2, lc = (tid & 3) * 4;

    float acc[4][4];
#pragma unroll
    for (int i = 0; i < 4; i++)
#pragma unroll
        for (int j = 0; j < 4; j++) acc[i][j] = 0.f;

    for (int c0 = 0; c0 < kC; c0 += 16) {
        float4 pv = *(const float4*)(p1 + (size_t)lr * kC + c0 + lc);
        float4 vv = *(const float4*)(wv + (size_t)lr * kC + c0 + lc);
        __syncthreads();
        ps[lc+0][lr]=pv.x; ps[lc+1][lr]=pv.y; ps[lc+2][lr]=pv.z; ps[lc+3][lr]=pv.w;
        vs[lc+0][lr]=vv.x; vs[lc+1][lr]=vv.y; vs[lc+2][lr]=vv.z; vs[lc+3][lr]=vv.w;
        __syncthreads();
#pragma unroll
        for (int cc = 0; cc < 16; cc++) {
            float a[4], v[4];
#pragma unroll
            for (int i = 0; i < 4; i++) a[i] = ps[cc][ty * 4 + i];
#pragma unroll
            for (int j = 0; j < 4; j++) v[j] = vs[cc][tx * 4 + j];
#pragma unroll
            for (int i = 0; i < 4; i++)
#pragma unroll
                for (int j = 0; j < 4; j++)
                    acc[i][j] += a[i] * v[j];
        }
    }

    __syncthreads();
#pragma unroll
    for (int i = 0; i < 4; i++)
#pragma unroll
        for (int j = 0; j < 4; j++)
            ls[ty * 4 + i][tx * 4 + j] = acc[i][j];
    __syncthreads();

    const int warp = tid >> 5, lane = tid & 31;
    float* arow_base = attn + (size_t)(b * 8 + h) * 4096;
    for (int r = 0; r < 8; r++) {
        const int d = warp * 8 + r;
        float v1 = kScale * ls[d][lane];
        float v2 = kScale * ls[d][lane + 32];
        float m = fmaxf(v1, v2);
#pragma unroll
        for (int s = 16; s > 0; s >>= 1)
            m = fmaxf(m, __shfl_xor_sync(0xffffffffu, m, s));
        float e1 = expf(v1 - m), e2 = expf(v2 - m);
        float sm = e1 + e2;
#pragma unroll
        for (int s = 16; s > 0; s >>= 1)
            sm += __shfl_xor_sync(0xffffffffu, sm, s);
        float inv = 1.f / sm;
        arow_base[d * 64 + lane]      = e1 * inv;
        arow_base[d * 64 + lane + 32] = e2 * inv;
    }
}

// ---------------------------------------------------------------------------
// Wht_b[c][h*64+d] = sum_e attn_h[d,e] * Wq[h*64+e][c]   (transposed What)
// grid (head, batch). smem: attn tile + 64x128 Wq chunk.
// ---------------------------------------------------------------------------
static constexpr int kWhatSmem = (64 * 68 + 64 * 132) * 4;   // 51200 B

__global__ __launch_bounds__(256) void what_t(
    const float* __restrict__ attn, const float* __restrict__ Wqkv,
    float* __restrict__ wht)
{
    extern __shared__ __align__(16) float ws[];
    float (*at)[68]  = (float(*)[68])ws;               // [64][68]
    float (*wq)[132] = (float(*)[132])(ws + 64 * 68);  // [64][132]

    const int h = blockIdx.x, b = blockIdx.y;
    const float* ag = attn + (size_t)(b * 8 + h) * 4096;
    const float* Wq = Wqkv + (size_t)(h * 64) * kC;
    float* out = wht + (size_t)b * kC * kC;

    const int tid = threadIdx.x;
    for (int i = tid; i < 4096; i += 256)
        at[i >> 6][i & 63] = ag[i];

    const int dG = (tid & 15) * 4;    // 4 consecutive d
    const int cB = tid >> 4;          // 8 c's: cB*8..cB*8+7

    for (int cb = 0; cb < 4; cb++) {
        __syncthreads();
        // load Wq[e][cb*128 .. +128) into wq
        for (int i = 0; i < 8; i++) {
            const int f4 = tid + i * 256;          // 2048 float4
            const int e  = f4 >> 5;
            const int cq = (f4 & 31) * 4;
            *(float4*)&wq[e][cq] =
                *(const float4*)(Wq + (size_t)e * kC + cb * 128 + cq);
        }
        __syncthreads();

        float o[8][4];
#pragma unroll
        for (int i = 0; i < 8; i++)
#pragma unroll
            for (int j = 0; j < 4; j++) o[i][j] = 0.f;

#pragma unroll 4
        for (int e = 0; e < 64; e++) {
            float a[4], w[8];
#pragma unroll
            for (int j = 0; j < 4; j++) a[j] = at[dG + j][e];
#pragma unroll
            for (int i = 0; i < 8; i++) w[i] = wq[e][cB * 8 + i];
#pragma unroll
            for (int i = 0; i < 8; i++)
#pragma unroll
                for (int j = 0; j < 4; j++)
                    o[i][j] += w[i] * a[j];
        }

#pragma unroll
        for (int i = 0; i < 8; i++) {
            const int c = cb * 128 + cB * 8 + i;
            *(float4*)(out + (size_t)c * kC + h * 64 + dG) =
                make_float4(o[i][0], o[i][1], o[i][2], o[i][3]);
        }
    }
}

// ---------------------------------------------------------------------------
// y = X @ Wt_b^T + bproj   (bf16x3 mma.sync, 3-stage cp.async, 2 CTA/SM)
// grid (N/128, 8192/128, batch). Stage: Ah|Al|Bh|Bl each 128x24 bf16 rows.
// ---------------------------------------------------------------------------
static constexpr int kYStage = 4 * 128 * 24 * 2;   // 24576 B
static constexpr int kYSmem  = 3 * kYStage;        // 73728 B

__global__ __launch_bounds__(256, 2) void gemm_y(
    const __nv_bfloat16* __restrict__ Xhi, const __nv_bfloat16* __restrict__ Xlo,
    const __nv_bfloat16* __restrict__ Bhi, const __nv_bfloat16* __restrict__ Blo,
    const float* __restrict__ bias, float* __restrict__ C)
{
    extern __shared__ __align__(16) char smem[];
    const uint32_t sbase = (uint32_t)__cvta_generic_to_shared(smem);

    const int tid = threadIdx.x, wid = tid >> 5, lane = tid & 31;
    const int n0 = blockIdx.x * 128;
    const int m0 = blockIdx.y * 128;
    const int b  = blockIdx.z;
    const int wm = (wid >> 1) * 32, wn = (wid & 1) * 64;

    const __nv_bfloat16* Ah = Xhi + (size_t)(b * kTok + m0) * kC;
    const __nv_bfloat16* Al = Xlo + (size_t)(b * kTok + m0) * kC;
    const __nv_bfloat16* Bh = Bhi + (size_t)b * kC * kC + (size_t)n0 * kC;
    const __nv_bfloat16* Bl = Blo + (size_t)b * kC * kC + (size_t)n0 * kC;

    const int lrow = tid >> 1;          // 0..127
    const int lk8  = (tid & 1) * 8;     // 0 or 8

    auto issue = [&](int kt) {
        const uint32_t stg = sbase + (uint32_t)(kt % 3) * kYStage;
        const uint32_t d = (uint32_t)(lrow * 24 + lk8) * 2;
        const size_t ro = (size_t)lrow * kC + kt * 16 + lk8;
        cp16(stg +          d, Ah + ro);
        cp16(stg + 6144u  + d, Al + ro);
        cp16(stg + 12288u + d, Bh + ro);
        cp16(stg + 18432u + d, Bl + ro);
        cp_commit();
    };

    const int aRow = lane & 15;
    const int aKof = (lane >> 4) * 8;
    const int bRow = (lane & 7) + ((lane >> 4) & 1) * 8;
    const int bKof = ((lane >> 3) & 1) * 8;

    float acc[2][8][4];
#pragma unroll
    for (int mt = 0; mt < 2; mt++)
#pragma unroll
        for (int nt = 0; nt < 8; nt++)
#pragma unroll
            for (int i = 0; i < 4; i++) acc[mt][nt][i] = 0.f;

    const int NK = kC / 16;   // 32
    issue(0); issue(1);

#pragma unroll 1
    for (int kt = 0; kt < NK; kt++) {
        cp_wait<1>();
        __syncthreads();
        if (kt + 2 < NK) issue(kt + 2);
        else             cp_commit();

        const uint32_t stg = sbase + (uint32_t)(kt % 3) * kYStage;
        uint32_t ahi[2][4], alo[2][4];
#pragma unroll
        for (int mt = 0; mt < 2; mt++) {
            const uint32_t co = (uint32_t)((wm + mt * 16 + aRow) * 24 + aKof) * 2;
            ldsm_x4(stg +         co, ahi[mt]);
            ldsm_x4(stg + 6144u + co, alo[mt]);
        }
#pragma unroll
        for (int ng = 0; ng < 4; ng++) {
            uint32_t bh[4], bl[4];
            const uint32_t co = (uint32_t)((wn + ng * 16 + bRow) * 24 + bKof) * 2;
            ldsm_x4(stg + 12288u + co, bh);
            ldsm_x4(stg + 18432u + co, bl);
#pragma unroll
            for (int mt = 0; mt < 2; mt++) {
#pragma unroll
                for (int j = 0; j < 2; j++) {
                    float* c = acc[mt][ng * 2 + j];
                    mma16816(c, ahi[mt], bh[2 * j], bh[2 * j + 1]);
                    mma16816(c, ahi[mt], bl[2 * j], bl[2 * j + 1]);
                    mma16816(c, alo[mt], bh[2 * j], bh[2 * j + 1]);
                }
            }
        }
    }

    const int g = lane >> 2, tg = lane & 3;
#pragma unroll
    for (int mt = 0; mt < 2; mt++) {
#pragma unroll
        for (int nt = 0; nt < 8; nt++) {
            const int r   = b * kTok + m0 + wm + mt * 16 + g;
            const int col = n0 + wn + nt * 8 + tg * 2;
            const float b0 = bias[col], b1 = bias[col + 1];
            *(float2*)(C + (size_t)r * kC + col) =
                make_float2(acc[mt][nt][0] + b0, acc[mt][nt][1] + b1);
            *(float2*)(C + (size_t)(r + 8) * kC + col) =
                make_float2(acc[mt][nt][2] + b0, acc[mt][nt][3] + b1);
        }
    }
}

// ---------------------------------------------------------------------------
extern "C" void kernel_launch(void* const* d_in, const int* in_sizes, int n_in,
                              void* d_out, int out_size)
{
    const float* x     = (const float*)d_in[0];
    const float* Wqkv  = (const float*)d_in[1];
    const float* Wproj = (const float*)d_in[2];
    const float* bproj = (const float*)d_in[3];
    float* out = (float*)d_out;

    __nv_bfloat16 *xh, *xl, *wth, *wtl;
    float *gpart, *G, *P1, *attn, *wht, *wt;
    cudaGetSymbolAddress((void**)&xh,    g_xh);
    cudaGetSymbolAddress((void**)&xl,    g_xl);
    cudaGetSymbolAddress((void**)&gpart, g_gpart);
    cudaGetSymbolAddress((void**)&G,     g_G);
    cudaGetSymbolAddress((void**)&P1,    g_P1);
    cudaGetSymbolAddress((void**)&attn,  g_attn);
    cudaGetSymbolAddress((void**)&wht,   g_wht);
    cudaGetSymbolAddress((void**)&wt,    g_wt);
    cudaGetSymbolAddress((void**)&wth,   g_wth);
    cudaGetSymbolAddress((void**)&wtl,   g_wtl);

    cudaFuncSetAttribute(gemm_gram,
        cudaFuncAttributeMaxDynamicSharedMemorySize, kGramSmem);
    cudaFuncSetAttribute(what_t,
        cudaFuncAttributeMaxDynamicSharedMemorySize, kWhatSmem);
    cudaFuncSetAttribute(gemm_y,
        cudaFuncAttributeMaxDynamicSharedMemorySize, kYSmem);

    // 1) split X
    {
        int n4 = kM * kC / 4;
        split_f32<<<(n4 + 255) / 256, 256>>>(x, xh, xl, n4);
    }

    // 2) Gram partials (upper-triangle channel blocks, split-K 4)
    gemm_gram<<<dim3(10, 16), 256, kGramSmem>>>(xh, xl, gpart);

    // 3) reduce + mirror -> symmetric G
    reduce_g<<<(4 * kC * kC) / 256, 256>>>(gpart, G);

    // 4) P1_b = Wk @ G_b  (G symmetric => A@B^T form exact)
    gemm_abT_z<<<dim3(4, 4, 4), 256>>>(
        Wqkv + (size_t)512 * kC, kC, 0,
        G, kC, (size_t)kC * kC,
        P1, kC, (size_t)kC * kC, kC);

    // 5) logits + softmax -> attn
    logits_softmax<<<dim3(8, 4), 256>>>(P1, Wqkv, attn);

    // 6) Wht_b = (attn_h @ Wq_h)^T
    what_t<<<dim3(8, 4), 256, kWhatSmem>>>(attn, Wqkv, wht);

    // 7) Wt_b = Wproj @ Wht_b^T  => gemm_abT(Wproj, Wht)
    gemm_abT_z<<<dim3(4, 4, 4), 256>>>(
        Wproj, kC, 0,
        wht, kC, (size_t)kC * kC,
        wt, kC, (size_t)kC * kC, kC);

    // 8) split Wt
    {
        int n4 = 4 * kC * kC / 4;
        split_f32<<<(n4 + 255) / 256, 256>>>(wt, wth, wtl, n4);
    }

    // 9) y = X @ Wt^T + bproj
    gemm_y<<<dim3(kC / 128, kTok / 128, 4), 256, kYSmem>>>(
        xh, xl, wth, wtl, bproj, out);
}

// round 8
// speedup vs baseline: 1.9440x; 1.1599x over previous
#include <cuda_runtime.h>
#include <cuda_bf16.h>
#include <cstdint>
#include <cstddef>

// ---------------------------------------------------------------------------
// ChannelAttention via Gram factorization (all heavy GEMMs on tensor cores):
//   G_b   = X_b^T X_b                       (bf16x3 mma, ldmatrix.trans)
//   P1_b  = Wk @ G_b                        (bf16x3 mma)
//   logit = SCALE * P1_h @ Wv_h^T, softmax  (FFMA, tiny)
//   Wht_b = (attn_h @ Wq_h)^T               (FFMA, tiny, emits bf16 hi/lo)
//   Wt_b  = Wproj @ Wht_b^T                 (bf16x3 mma, emits bf16 hi/lo)
//   y     = X @ Wt_b^T + bproj              (bf16x3 mma)
// ---------------------------------------------------------------------------

static constexpr int   kTok   = 8192;
static constexpr int   kC     = 512;
static constexpr int   kM     = 4 * kTok;       // 32768
static constexpr float kScale = 0.125f;
static constexpr int   kSplitK = 4;             // gram split-K
static constexpr int   kKS     = kTok / kSplitK;  // 2048 tokens per split

// Scratch (device globals; all read locations rewritten each launch)
__device__ __nv_bfloat16 g_xh [(size_t)kM * kC];
__device__ __nv_bfloat16 g_xl [(size_t)kM * kC];
__device__ float g_gpart[(size_t)kSplitK * 4 * kC * kC];
__device__ __nv_bfloat16 g_Gh [(size_t)4 * kC * kC];
__device__ __nv_bfloat16 g_Gl [(size_t)4 * kC * kC];
__device__ float g_P1   [(size_t)4 * kC * kC];
__device__ float g_attn [(size_t)32 * 64 * 64];
__device__ __nv_bfloat16 g_whth[(size_t)4 * kC * kC];
__device__ __nv_bfloat16 g_whtl[(size_t)4 * kC * kC];
__device__ __nv_bfloat16 g_wth[(size_t)4 * kC * kC];
__device__ __nv_bfloat16 g_wtl[(size_t)4 * kC * kC];
__device__ __nv_bfloat16 g_wkh[(size_t)kC * kC];
__device__ __nv_bfloat16 g_wkl[(size_t)kC * kC];
__device__ __nv_bfloat16 g_wph[(size_t)kC * kC];
__device__ __nv_bfloat16 g_wpl[(size_t)kC * kC];

// ---------------------------------------------------------------------------
// primitives
// ---------------------------------------------------------------------------
__device__ __forceinline__ void ldsm_x4(uint32_t addr, uint32_t* r)
{
    asm volatile("ldmatrix.sync.aligned.m8n8.x4.shared.b16 {%0,%1,%2,%3}, [%4];\n"
                 : "=r"(r[0]), "=r"(r[1]), "=r"(r[2]), "=r"(r[3]) : "r"(addr));
}
__device__ __forceinline__ void ldsm_x4_t(uint32_t addr, uint32_t* r)
{
    asm volatile("ldmatrix.sync.aligned.m8n8.x4.trans.shared.b16 {%0,%1,%2,%3}, [%4];\n"
                 : "=r"(r[0]), "=r"(r[1]), "=r"(r[2]), "=r"(r[3]) : "r"(addr));
}
__device__ __forceinline__ void mma16816(float* c, const uint32_t* a,
                                         uint32_t b0, uint32_t b1)
{
    asm volatile(
        "mma.sync.aligned.m16n8k16.row.col.f32.bf16.bf16.f32 "
        "{%0,%1,%2,%3}, {%4,%5,%6,%7}, {%8,%9}, {%0,%1,%2,%3};\n"
        : "+f"(c[0]), "+f"(c[1]), "+f"(c[2]), "+f"(c[3])
        : "r"(a[0]), "r"(a[1]), "r"(a[2]), "r"(a[3]), "r"(b0), "r"(b1));
}
__device__ __forceinline__ void cp16(uint32_t dst, const void* src)
{
    asm volatile("cp.async.cg.shared.global [%0], [%1], 16;\n" :: "r"(dst), "l"(src));
}
__device__ __forceinline__ void cp_commit()
{
    asm volatile("cp.async.commit_group;\n");
}
template <int N> __device__ __forceinline__ void cp_wait()
{
    asm volatile("cp.async.wait_group %0;\n" :: "n"(N));
}
__device__ __forceinline__ uint32_t pack_hi2(float a, float b)
{
    __nv_bfloat162 p;
    p.x = __float2bfloat16_rn(a);
    p.y = __float2bfloat16_rn(b);
    return *reinterpret_cast<uint32_t*>(&p);
}
__device__ __forceinline__ uint32_t pack_lo2(float a, float b, uint32_t hi)
{
    __nv_bfloat162 h = *reinterpret_cast<__nv_bfloat162*>(&hi);
    __nv_bfloat162 p;
    p.x = __float2bfloat16_rn(a - __bfloat162float(h.x));
    p.y = __float2bfloat16_rn(b - __bfloat162float(h.y));
    return *reinterpret_cast<uint32_t*>(&p);
}

// ---------------------------------------------------------------------------
// fp32 -> (hi, lo) bf16 split
// ---------------------------------------------------------------------------
__global__ __launch_bounds__(256) void split_f32(
    const float* __restrict__ src,
    __nv_bfloat16* __restrict__ hi, __nv_bfloat16* __restrict__ lo, int n4)
{
    int i = blockIdx.x * blockDim.x + threadIdx.x;
    if (i >= n4) return;
    float4 f = ((const float4*)src)[i];
    float a[4] = {f.x, f.y, f.z, f.w};
    __nv_bfloat16 h[4], l[4];
#pragma unroll
    for (int j = 0; j < 4; j++) {
        h[j] = __float2bfloat16_rn(a[j]);
        l[j] = __float2bfloat16_rn(a[j] - __bfloat162float(h[j]));
    }
    ((uint2*)hi)[i] = *(uint2*)h;
    ((uint2*)lo)[i] = *(uint2*)l;
}

// ---------------------------------------------------------------------------
// Gram partials (bf16x3, ldmatrix.trans) — round-6 validated.
// ---------------------------------------------------------------------------
static constexpr int kGramStage = 4 * 16 * 136 * 2;   // 17408 B
static constexpr int kGramSmem  = 3 * kGramStage;     // 52224 B

__global__ __launch_bounds__(256, 2) void gemm_gram(
    const __nv_bfloat16* __restrict__ Xhi,
    const __nv_bfloat16* __restrict__ Xlo,
    float* __restrict__ part)
{
    extern __shared__ __align__(16) char smem[];
    const uint32_t sbase = (uint32_t)__cvta_generic_to_shared(smem);

    int p = blockIdx.x, mb = 0;
    while (p >= 4 - mb) { p -= 4 - mb; mb++; }
    const int m0 = mb * 128, n0 = (mb + p) * 128;
    const int bz = blockIdx.y;
    const int b = bz >> 2, s = bz & 3;
    const size_t tokBase = (size_t)b * kTok + (size_t)s * kKS;

    const int tid = threadIdx.x, wid = tid >> 5, lane = tid & 31;
    const int wm = (wid >> 1) * 32, wn = (wid & 1) * 64;

    const int lrow = tid >> 4;
    const int lch  = (tid & 15) * 8;

    auto issue = [&](int kt) {
        const uint32_t stg = sbase + (uint32_t)(kt % 3) * kGramStage;
        const size_t ro = (tokBase + (size_t)kt * 16 + lrow) * kC;
        const uint32_t d = (uint32_t)(lrow * 136 + lch) * 2;
        cp16(stg +          d, Xhi + ro + m0 + lch);
        cp16(stg + 4352u  + d, Xlo + ro + m0 + lch);
        cp16(stg + 8704u  + d, Xhi + ro + n0 + lch);
        cp16(stg + 13056u + d, Xlo + ro + n0 + lch);
        cp_commit();
    };

    const int kA = (lane & 7) + ((lane >> 4) & 1) * 8;
    const int mA = ((lane >> 3) & 1) * 8;
    const int kB = (lane & 7) + ((lane >> 3) & 1) * 8;
    const int nB = ((lane >> 4) & 1) * 8;

    float acc[2][8][4];
#pragma unroll
    for (int mt = 0; mt < 2; mt++)
#pragma unroll
        for (int nt = 0; nt < 8; nt++)
#pragma unroll
            for (int i = 0; i < 4; i++) acc[mt][nt][i] = 0.f;

    const int NK = kKS / 16;
    issue(0); issue(1);

#pragma unroll 1
    for (int kt = 0; kt < NK; kt++) {
        cp_wait<1>();
        __syncthreads();
        if (kt + 2 < NK) issue(kt + 2);
        else             cp_commit();

        const uint32_t stg = sbase + (uint32_t)(kt % 3) * kGramStage;
        uint32_t ahi[2][4], alo[2][4];
#pragma unroll
        for (int mt = 0; mt < 2; mt++) {
            const uint32_t co = (uint32_t)(kA * 136 + wm + mt * 16 + mA) * 2;
            ldsm_x4_t(stg +         co, ahi[mt]);
            ldsm_x4_t(stg + 4352u + co, alo[mt]);
        }
#pragma unroll
        for (int ng = 0; ng < 4; ng++) {
            uint32_t bh[4], bl[4];
            const uint32_t co = (uint32_t)(kB * 136 + wn + ng * 16 + nB) * 2;
            ldsm_x4_t(stg + 8704u  + co, bh);
            ldsm_x4_t(stg + 13056u + co, bl);
#pragma unroll
            for (int mt = 0; mt < 2; mt++) {
#pragma unroll
                for (int j = 0; j < 2; j++) {
                    float* c = acc[mt][ng * 2 + j];
                    mma16816(c, ahi[mt], bh[2 * j], bh[2 * j + 1]);
                    mma16816(c, ahi[mt], bl[2 * j], bl[2 * j + 1]);
                    mma16816(c, alo[mt], bh[2 * j], bh[2 * j + 1]);
                }
            }
        }
    }

    const int g = lane >> 2, tg = lane & 3;
    float* P = part + (size_t)(s * 4 + b) * kC * kC;
#pragma unroll
    for (int mt = 0; mt < 2; mt++) {
#pragma unroll
        for (int nt = 0; nt < 8; nt++) {
            const int r   = m0 + wm + mt * 16 + g;
            const int col = n0 + wn + nt * 8 + tg * 2;
            *(float2*)(P + (size_t)r * kC + col) =
                make_float2(acc[mt][nt][0], acc[mt][nt][1]);
            *(float2*)(P + (size_t)(r + 8) * kC + col) =
                make_float2(acc[mt][nt][2], acc[mt][nt][3]);
        }
    }
}

// ---------------------------------------------------------------------------
// Reduce split-K partials with symmetric mirroring -> G as bf16 hi/lo.
// ---------------------------------------------------------------------------
__global__ __launch_bounds__(256) void reduce_g(
    const float* __restrict__ part,
    __nv_bfloat16* __restrict__ Gh, __nv_bfloat16* __restrict__ Gl)
{
    const int i = blockIdx.x * 256 + threadIdx.x;
    const int b = i >> 18;
    const int r = (i >> 9) & 511;
    const int c = i & 511;
    const size_t src = ((r >> 7) <= (c >> 7))
        ? ((size_t)r * kC + c) : ((size_t)c * kC + r);
    float sum = 0.f;
#pragma unroll
    for (int s = 0; s < kSplitK; s++)
        sum += part[(size_t)(s * 4 + b) * kC * kC + src];
    const size_t o = (size_t)b * kC * kC + (size_t)r * kC + c;
    __nv_bfloat16 h = __float2bfloat16_rn(sum);
    Gh[o] = h;
    Gl[o] = __float2bfloat16_rn(sum - __bfloat162float(h));
}

// ---------------------------------------------------------------------------
// bf16x3 tensor GEMM: C = A @ B^T, 128x128 tile, K=512, batched over z.
// outF != nullptr -> fp32 output; else (outH,outL) bf16 hi/lo split output.
// Stage: Ah|Al|Bh|Bl each 128x24 bf16 rows (24576 B); 3 stages.
// ---------------------------------------------------------------------------
static constexpr int kYStage = 4 * 128 * 24 * 2;   // 24576 B
static constexpr int kYSmem  = 3 * kYStage;        // 73728 B

__global__ __launch_bounds__(256, 2) void gemm_tcz(
    const __nv_bfloat16* __restrict__ Ahi, const __nv_bfloat16* __restrict__ Alo,
    size_t strideA,
    const __nv_bfloat16* __restrict__ Bhi, const __nv_bfloat16* __restrict__ Blo,
    size_t strideB,
    const float* __restrict__ bias,
    float* __restrict__ outF,
    __nv_bfloat16* __restrict__ outH, __nv_bfloat16* __restrict__ outL,
    int ldc, size_t strideC)
{
    extern __shared__ __align__(16) char smem[];
    const uint32_t sbase = (uint32_t)__cvta_generic_to_shared(smem);

    const int tid = threadIdx.x, wid = tid >> 5, lane = tid & 31;
    const int n0 = blockIdx.x * 128;
    const int m0 = blockIdx.y * 128;
    const int z  = blockIdx.z;
    const int wm = (wid >> 1) * 32, wn = (wid & 1) * 64;

    const __nv_bfloat16* Ah = Ahi + strideA * z + (size_t)m0 * kC;
    const __nv_bfloat16* Al = Alo + strideA * z + (size_t)m0 * kC;
    const __nv_bfloat16* Bh = Bhi + strideB * z + (size_t)n0 * kC;
    const __nv_bfloat16* Bl = Blo + strideB * z + (size_t)n0 * kC;

    const int lrow = tid >> 1;
    const int lk8  = (tid & 1) * 8;

    auto issue = [&](int kt) {
        const uint32_t stg = sbase + (uint32_t)(kt % 3) * kYStage;
        const uint32_t d = (uint32_t)(lrow * 24 + lk8) * 2;
        const size_t ro = (size_t)lrow * kC + kt * 16 + lk8;
        cp16(stg +          d, Ah + ro);
        cp16(stg + 6144u  + d, Al + ro);
        cp16(stg + 12288u + d, Bh + ro);
        cp16(stg + 18432u + d, Bl + ro);
        cp_commit();
    };

    const int aRow = lane & 15;
    const int aKof = (lane >> 4) * 8;
    const int bRow = (lane & 7) + ((lane >> 4) & 1) * 8;
    const int bKof = ((lane >> 3) & 1) * 8;

    float acc[2][8][4];
#pragma unroll
    for (int mt = 0; mt < 2; mt++)
#pragma unroll
        for (int nt = 0; nt < 8; nt++)
#pragma unroll
            for (int i = 0; i < 4; i++) acc[mt][nt][i] = 0.f;

    const int NK = kC / 16;   // 32
    issue(0); issue(1);

#pragma unroll 1
    for (int kt = 0; kt < NK; kt++) {
        cp_wait<1>();
        __syncthreads();
        if (kt + 2 < NK) issue(kt + 2);
        else             cp_commit();

        const uint32_t stg = sbase + (uint32_t)(kt % 3) * kYStage;
        uint32_t ahi[2][4], alo[2][4];
#pragma unroll
        for (int mt = 0; mt < 2; mt++) {
            const uint32_t co = (uint32_t)((wm + mt * 16 + aRow) * 24 + aKof) * 2;
            ldsm_x4(stg +         co, ahi[mt]);
            ldsm_x4(stg + 6144u + co, alo[mt]);
        }
#pragma unroll
        for (int ng = 0; ng < 4; ng++) {
            uint32_t bh[4], bl[4];
            const uint32_t co = (uint32_t)((wn + ng * 16 + bRow) * 24 + bKof) * 2;
            ldsm_x4(stg + 12288u + co, bh);
            ldsm_x4(stg + 18432u + co, bl);
#pragma unroll
            for (int mt = 0; mt < 2; mt++) {
#pragma unroll
                for (int j = 0; j < 2; j++) {
                    float* c = acc[mt][ng * 2 + j];
                    mma16816(c, ahi[mt], bh[2 * j], bh[2 * j + 1]);
                    mma16816(c, ahi[mt], bl[2 * j], bl[2 * j + 1]);
                    mma16816(c, alo[mt], bh[2 * j], bh[2 * j + 1]);
                }
            }
        }
    }

    const int g = lane >> 2, tg = lane & 3;
#pragma unroll
    for (int mt = 0; mt < 2; mt++) {
#pragma unroll
        for (int nt = 0; nt < 8; nt++) {
            const int r   = m0 + wm + mt * 16 + g;
            const int col = n0 + wn + nt * 8 + tg * 2;
            float v0 = acc[mt][nt][0], v1 = acc[mt][nt][1];
            float v2 = acc[mt][nt][2], v3 = acc[mt][nt][3];
            if (bias) {
                v0 += bias[col]; v1 += bias[col + 1];
                v2 += bias[col]; v3 += bias[col + 1];
            }
            const size_t o0 = strideC * z + (size_t)r * ldc + col;
            const size_t o1 = strideC * z + (size_t)(r + 8) * ldc + col;
            if (outF) {
                *(float2*)(outF + o0) = make_float2(v0, v1);
                *(float2*)(outF + o1) = make_float2(v2, v3);
            } else {
                uint32_t h0 = pack_hi2(v0, v1), h1 = pack_hi2(v2, v3);
                *(uint32_t*)(outH + o0) = h0;
                *(uint32_t*)(outH + o1) = h1;
                *(uint32_t*)(outL + o0) = pack_lo2(v0, v1, h0);
                *(uint32_t*)(outL + o1) = pack_lo2(v2, v3, h1);
            }
        }
    }
}

// ---------------------------------------------------------------------------
// logits_h = SCALE * P1_h @ Wv_h^T (64x64, K=512), row softmax -> attn.
// ---------------------------------------------------------------------------
__global__ __launch_bounds__(256) void logits_softmax(
    const float* __restrict__ P1, const float* __restrict__ Wqkv,
    float* __restrict__ attn)
{
    const int h = blockIdx.x, b = blockIdx.y;
    const float* p1 = P1 + (size_t)b * kC * kC + (size_t)(h * 64) * kC;
    const float* wv = Wqkv + (size_t)(1024 + h * 64) * kC;

    __shared__ float ps[16][68];
    __shared__ float vs[16][68];
    __shared__ float ls[64][68];

    const int tid = threadIdx.x;
    const int ty = tid >> 4, tx = tid & 15;
    const int lr = tid >> 2, lc = (tid & 3) * 4;

    float acc[4][4];
#pragma unroll
    for (int i = 0; i < 4; i++)
#pragma unroll
        for (int j = 0; j < 4; j++) acc[i][j] = 0.f;

    for (int c0 = 0; c0 < kC; c0 += 16) {
        float4 pv = *(const float4*)(p1 + (size_t)lr * kC + c0 + lc);
        float4 vv = *(const float4*)(wv + (size_t)lr * kC + c0 + lc);
        __syncthreads();
        ps[lc+0][lr]=pv.x; ps[lc+1][lr]=pv.y; ps[lc+2][lr]=pv.z; ps[lc+3][lr]=pv.w;
        vs[lc+0][lr]=vv.x; vs[lc+1][lr]=vv.y; vs[lc+2][lr]=vv.z; vs[lc+3][lr]=vv.w;
        __syncthreads();
#pragma unroll
        for (int cc = 0; cc < 16; cc++) {
            float a[4], v[4];
#pragma unroll
            for (int i = 0; i < 4; i++) a[i] = ps[cc][ty * 4 + i];
#pragma unroll
            for (int j = 0; j < 4; j++) v[j] = vs[cc][tx * 4 + j];
#pragma unroll
            for (int i = 0; i < 4; i++)
#pragma unroll
                for (int j = 0; j < 4; j++)
                    acc[i][j] += a[i] * v[j];
        }
    }

    __syncthreads();
#pragma unroll
    for (int i = 0; i < 4; i++)
#pragma unroll
        for (int j = 0; j < 4; j++)
            ls[ty * 4 + i][tx * 4 + j] = acc[i][j];
    __syncthreads();

    const int warp = tid >> 5, lane = tid & 31;
    float* arow_base = attn + (size_t)(b * 8 + h) * 4096;
    for (int r = 0; r < 8; r++) {
        const int d = warp * 8 + r;
        float v1 = kScale * ls[d][lane];
        float v2 = kScale * ls[d][lane + 32];
        float m = fmaxf(v1, v2);
#pragma unroll
        for (int s = 16; s > 0; s >>= 1)
            m = fmaxf(m, __shfl_xor_sync(0xffffffffu, m, s));
        float e1 = expf(v1 - m), e2 = expf(v2 - m);
        float sm = e1 + e2;
#pragma unroll
        for (int s = 16; s > 0; s >>= 1)
            sm += __shfl_xor_sync(0xffffffffu, sm, s);
        float inv = 1.f / sm;
        arow_base[d * 64 + lane]      = e1 * inv;
        arow_base[d * 64 + lane + 32] = e2 * inv;
    }
}

// ---------------------------------------------------------------------------
// Wht_b[c][h*64+d] = sum_e attn_h[d,e] * Wq[h*64+e][c] -> bf16 hi/lo.
// ---------------------------------------------------------------------------
static constexpr int kWhatSmem = (64 * 68 + 64 * 132) * 4;

__global__ __launch_bounds__(256) void what_t(
    const float* __restrict__ attn, const float* __restrict__ Wqkv,
    __nv_bfloat16* __restrict__ whth, __nv_bfloat16* __restrict__ whtl)
{
    extern __shared__ __align__(16) float ws[];
    float (*at)[68]  = (float(*)[68])ws;
    float (*wq)[132] = (float(*)[132])(ws + 64 * 68);

    const int h = blockIdx.x, b = blockIdx.y;
    const float* ag = attn + (size_t)(b * 8 + h) * 4096;
    const float* Wq = Wqkv + (size_t)(h * 64) * kC;
    const size_t obase = (size_t)b * kC * kC;

    const int tid = threadIdx.x;
    for (int i = tid; i < 4096; i += 256)
        at[i >> 6][i & 63] = ag[i];

    const int dG = (tid & 15) * 4;
    const int cB = tid >> 4;

    for (int cb = 0; cb < 4; cb++) {
        __syncthreads();
        for (int i = 0; i < 8; i++) {
            const int f4 = tid + i * 256;
            const int e  = f4 >> 5;
            const int cq = (f4 & 31) * 4;
            *(float4*)&wq[e][cq] =
                *(const float4*)(Wq + (size_t)e * kC + cb * 128 + cq);
        }
        __syncthreads();

        float o[8][4];
#pragma unroll
        for (int i = 0; i < 8; i++)
#pragma unroll
            for (int j = 0; j < 4; j++) o[i][j] = 0.f;

#pragma unroll 4
        for (int e = 0; e < 64; e++) {
            float a[4], w[8];
#pragma unroll
            for (int j = 0; j < 4; j++) a[j] = at[dG + j][e];
#pragma unroll
            for (int i = 0; i < 8; i++) w[i] = wq[e][cB * 8 + i];
#pragma unroll
            for (int i = 0; i < 8; i++)
#pragma unroll
                for (int j = 0; j < 4; j++)
                    o[i][j] += w[i] * a[j];
        }

#pragma unroll
        for (int i = 0; i < 8; i++) {
            const int c = cb * 128 + cB * 8 + i;
            const size_t oo = obase + (size_t)c * kC + h * 64 + dG;
            uint32_t h0 = pack_hi2(o[i][0], o[i][1]);
            uint32_t h1 = pack_hi2(o[i][2], o[i][3]);
            uint32_t l0 = pack_lo2(o[i][0], o[i][1], h0);
            uint32_t l1 = pack_lo2(o[i][2], o[i][3], h1);
            ((uint32_t*)(whth + oo))[0] = h0;
            ((uint32_t*)(whth + oo))[1] = h1;
            ((uint32_t*)(whtl + oo))[0] = l0;
            ((uint32_t*)(whtl + oo))[1] = l1;
        }
    }
}

// ---------------------------------------------------------------------------
extern "C" void kernel_launch(void* const* d_in, const int* in_sizes, int n_in,
                              void* d_out, int out_size)
{
    const float* x     = (const float*)d_in[0];
    const float* Wqkv  = (const float*)d_in[1];
    const float* Wproj = (const float*)d_in[2];
    const float* bproj = (const float*)d_in[3];
    float* out = (float*)d_out;

    __nv_bfloat16 *xh, *xl, *Gh, *Gl, *whth, *whtl, *wth, *wtl,
                  *wkh, *wkl, *wph, *wpl;
    float *gpart, *P1, *attn;
    cudaGetSymbolAddress((void**)&xh,    g_xh);
    cudaGetSymbolAddress((void**)&xl,    g_xl);
    cudaGetSymbolAddress((void**)&gpart, g_gpart);
    cudaGetSymbolAddress((void**)&Gh,    g_Gh);
    cudaGetSymbolAddress((void**)&Gl,    g_Gl);
    cudaGetSymbolAddress((void**)&P1,    g_P1);
    cudaGetSymbolAddress((void**)&attn,  g_attn);
    cudaGetSymbolAddress((void**)&whth,  g_whth);
    cudaGetSymbolAddress((void**)&whtl,  g_whtl);
    cudaGetSymbolAddress((void**)&wth,   g_wth);
    cudaGetSymbolAddress((void**)&wtl,   g_wtl);
    cudaGetSymbolAddress((void**)&wkh,   g_wkh);
    cudaGetSymbolAddress((void**)&wkl,   g_wkl);
    cudaGetSymbolAddress((void**)&wph,   g_wph);
    cudaGetSymbolAddress((void**)&wpl,   g_wpl);

    cudaFuncSetAttribute(gemm_gram,
        cudaFuncAttributeMaxDynamicSharedMemorySize, kGramSmem);
    cudaFuncSetAttribute(what_t,
        cudaFuncAttributeMaxDynamicSharedMemorySize, kWhatSmem);
    cudaFuncSetAttribute(gemm_tcz,
        cudaFuncAttributeMaxDynamicSharedMemorySize, kYSmem);

    const size_t cc = (size_t)kC * kC;

    // 1) splits: X, Wk (Wqkv rows 512..1024), Wproj
    split_f32<<<(kM * kC / 4 + 255) / 256, 256>>>(x, xh, xl, kM * kC / 4);
    split_f32<<<((int)cc / 4 + 255) / 256, 256>>>(Wqkv + cc, wkh, wkl, (int)cc / 4);
    split_f32<<<((int)cc / 4 + 255) / 256, 256>>>(Wproj, wph, wpl, (int)cc / 4);

    // 2) Gram partials
    gemm_gram<<<dim3(10, 16), 256, kGramSmem>>>(xh, xl, gpart);

    // 3) reduce + mirror -> G (bf16 hi/lo)
    reduce_g<<<(4 * (int)cc) / 256, 256>>>(gpart, Gh, Gl);

    // 4) P1_b = Wk @ G_b  (G symmetric)  [tensor, fp32 out]
    gemm_tcz<<<dim3(4, 4, 4), 256, kYSmem>>>(
        wkh, wkl, 0, Gh, Gl, cc, nullptr, P1, nullptr, nullptr, kC, cc);

    // 5) logits + softmax -> attn
    logits_softmax<<<dim3(8, 4), 256>>>(P1, Wqkv, attn);

    // 6) Wht_b = (attn_h @ Wq_h)^T  -> bf16 hi/lo
    what_t<<<dim3(8, 4), 256, kWhatSmem>>>(attn, Wqkv, whth, whtl);

    // 7) Wt_b = Wproj @ Wht_b^T  [tensor, bf16 hi/lo out]
    gemm_tcz<<<dim3(4, 4, 4), 256, kYSmem>>>(
        wph, wpl, 0, whth, whtl, cc, nullptr, nullptr, wth, wtl, kC, cc);

    // 8) y = X @ Wt_b^T + bproj  [tensor]
    gemm_tcz<<<dim3(4, kTok / 128, 4), 256, kYSmem>>>(
        xh, xl, (size_t)kTok * kC, wth, wtl, cc, bproj,
        out, nullptr, nullptr, kC, (size_t)kTok * kC);
}

// round 9
// speedup vs baseline: 2.0335x; 1.0460x over previous
#include <cuda_runtime.h>
#include <cuda_bf16.h>
#include <cstdint>
#include <cstddef>

// ---------------------------------------------------------------------------
// ChannelAttention via Gram factorization (all heavy GEMMs on tensor cores):
//   G_b   = X_b^T X_b                       (bf16x3 mma, ldmatrix.trans, split-K 8)
//   P1_b  = Wk @ G_b                        (bf16x3 mma)
//   logit = SCALE * P1_h @ Wv_h^T, softmax  (FFMA, tiny)
//   Wht_b = (attn_h @ Wq_h)^T               (FFMA, tiny, emits bf16 hi/lo)
//   Wt_b  = Wproj @ Wht_b^T                 (bf16x3 mma, emits bf16 hi/lo)
//   y     = X @ Wt_b^T + bproj              (bf16x3 mma)
// ---------------------------------------------------------------------------

static constexpr int   kTok   = 8192;
static constexpr int   kC     = 512;
static constexpr int   kM     = 4 * kTok;       // 32768
static constexpr float kScale = 0.125f;
static constexpr int   kSplitK = 8;             // gram split-K (grid 320 -> 2 CTA/SM)
static constexpr int   kKS     = kTok / kSplitK;  // 1024 tokens per split

// Scratch (device globals; all read locations rewritten each launch)
__device__ __nv_bfloat16 g_xh [(size_t)kM * kC];
__device__ __nv_bfloat16 g_xl [(size_t)kM * kC];
__device__ float g_gpart[(size_t)kSplitK * 4 * kC * kC];
__device__ __nv_bfloat16 g_Gh [(size_t)4 * kC * kC];
__device__ __nv_bfloat16 g_Gl [(size_t)4 * kC * kC];
__device__ float g_P1   [(size_t)4 * kC * kC];
__device__ float g_attn [(size_t)32 * 64 * 64];
__device__ __nv_bfloat16 g_whth[(size_t)4 * kC * kC];
__device__ __nv_bfloat16 g_whtl[(size_t)4 * kC * kC];
__device__ __nv_bfloat16 g_wth[(size_t)4 * kC * kC];
__device__ __nv_bfloat16 g_wtl[(size_t)4 * kC * kC];
__device__ __nv_bfloat16 g_wkh[(size_t)kC * kC];
__device__ __nv_bfloat16 g_wkl[(size_t)kC * kC];
__device__ __nv_bfloat16 g_wph[(size_t)kC * kC];
__device__ __nv_bfloat16 g_wpl[(size_t)kC * kC];

// ---------------------------------------------------------------------------
// primitives
// ---------------------------------------------------------------------------
__device__ __forceinline__ void ldsm_x4(uint32_t addr, uint32_t* r)
{
    asm volatile("ldmatrix.sync.aligned.m8n8.x4.shared.b16 {%0,%1,%2,%3}, [%4];\n"
                 : "=r"(r[0]), "=r"(r[1]), "=r"(r[2]), "=r"(r[3]) : "r"(addr));
}
__device__ __forceinline__ void ldsm_x4_t(uint32_t addr, uint32_t* r)
{
    asm volatile("ldmatrix.sync.aligned.m8n8.x4.trans.shared.b16 {%0,%1,%2,%3}, [%4];\n"
                 : "=r"(r[0]), "=r"(r[1]), "=r"(r[2]), "=r"(r[3]) : "r"(addr));
}
__device__ __forceinline__ void mma16816(float* c, const uint32_t* a,
                                         uint32_t b0, uint32_t b1)
{
    asm volatile(
        "mma.sync.aligned.m16n8k16.row.col.f32.bf16.bf16.f32 "
        "{%0,%1,%2,%3}, {%4,%5,%6,%7}, {%8,%9}, {%0,%1,%2,%3};\n"
        : "+f"(c[0]), "+f"(c[1]), "+f"(c[2]), "+f"(c[3])
        : "r"(a[0]), "r"(a[1]), "r"(a[2]), "r"(a[3]), "r"(b0), "r"(b1));
}
__device__ __forceinline__ void cp16(uint32_t dst, const void* src)
{
    asm volatile("cp.async.cg.shared.global [%0], [%1], 16;\n" :: "r"(dst), "l"(src));
}
__device__ __forceinline__ void cp_commit()
{
    asm volatile("cp.async.commit_group;\n");
}
template <int N> __device__ __forceinline__ void cp_wait()
{
    asm volatile("cp.async.wait_group %0;\n" :: "n"(N));
}
__device__ __forceinline__ uint32_t pack_hi2(float a, float b)
{
    __nv_bfloat162 p;
    p.x = __float2bfloat16_rn(a);
    p.y = __float2bfloat16_rn(b);
    return *reinterpret_cast<uint32_t*>(&p);
}
__device__ __forceinline__ uint32_t pack_lo2(float a, float b, uint32_t hi)
{
    __nv_bfloat162 h = *reinterpret_cast<__nv_bfloat162*>(&hi);
    __nv_bfloat162 p;
    p.x = __float2bfloat16_rn(a - __bfloat162float(h.x));
    p.y = __float2bfloat16_rn(b - __bfloat162float(h.y));
    return *reinterpret_cast<uint32_t*>(&p);
}

// ---------------------------------------------------------------------------
// fp32 -> (hi, lo) bf16 split
// ---------------------------------------------------------------------------
__global__ __launch_bounds__(256) void split_f32(
    const float* __restrict__ src,
    __nv_bfloat16* __restrict__ hi, __nv_bfloat16* __restrict__ lo, int n4)
{
    int i = blockIdx.x * blockDim.x + threadIdx.x;
    if (i >= n4) return;
    float4 f = ((const float4*)src)[i];
    float a[4] = {f.x, f.y, f.z, f.w};
    __nv_bfloat16 h[4], l[4];
#pragma unroll
    for (int j = 0; j < 4; j++) {
        h[j] = __float2bfloat16_rn(a[j]);
        l[j] = __float2bfloat16_rn(a[j] - __bfloat162float(h[j]));
    }
    ((uint2*)hi)[i] = *(uint2*)h;
    ((uint2*)lo)[i] = *(uint2*)l;
}

// ---------------------------------------------------------------------------
// Gram partials (bf16x3, ldmatrix.trans), split-K 8.
// ---------------------------------------------------------------------------
static constexpr int kGramStage = 4 * 16 * 136 * 2;   // 17408 B
static constexpr int kGramSmem  = 3 * kGramStage;     // 52224 B

__global__ __launch_bounds__(256, 2) void gemm_gram(
    const __nv_bfloat16* __restrict__ Xhi,
    const __nv_bfloat16* __restrict__ Xlo,
    float* __restrict__ part)
{
    extern __shared__ __align__(16) char smem[];
    const uint32_t sbase = (uint32_t)__cvta_generic_to_shared(smem);

    int p = blockIdx.x, mb = 0;
    while (p >= 4 - mb) { p -= 4 - mb; mb++; }
    const int m0 = mb * 128, n0 = (mb + p) * 128;
    const int bz = blockIdx.y;           // b*kSplitK + s
    const int b = bz >> 3, s = bz & 7;
    const size_t tokBase = (size_t)b * kTok + (size_t)s * kKS;

    const int tid = threadIdx.x, wid = tid >> 5, lane = tid & 31;
    const int wm = (wid >> 1) * 32, wn = (wid & 1) * 64;

    const int lrow = tid >> 4;
    const int lch  = (tid & 15) * 8;

    auto issue = [&](int kt) {
        const uint32_t stg = sbase + (uint32_t)(kt % 3) * kGramStage;
        const size_t ro = (tokBase + (size_t)kt * 16 + lrow) * kC;
        const uint32_t d = (uint32_t)(lrow * 136 + lch) * 2;
        cp16(stg +          d, Xhi + ro + m0 + lch);
        cp16(stg + 4352u  + d, Xlo + ro + m0 + lch);
        cp16(stg + 8704u  + d, Xhi + ro + n0 + lch);
        cp16(stg + 13056u + d, Xlo + ro + n0 + lch);
        cp_commit();
    };

    const int kA = (lane & 7) + ((lane >> 4) & 1) * 8;
    const int mA = ((lane >> 3) & 1) * 8;
    const int kB = (lane & 7) + ((lane >> 3) & 1) * 8;
    const int nB = ((lane >> 4) & 1) * 8;

    float acc[2][8][4];
#pragma unroll
    for (int mt = 0; mt < 2; mt++)
#pragma unroll
        for (int nt = 0; nt < 8; nt++)
#pragma unroll
            for (int i = 0; i < 4; i++) acc[mt][nt][i] = 0.f;

    const int NK = kKS / 16;   // 64
    issue(0); issue(1);

#pragma unroll 1
    for (int kt = 0; kt < NK; kt++) {
        cp_wait<1>();
        __syncthreads();
        if (kt + 2 < NK) issue(kt + 2);
        else             cp_commit();

        const uint32_t stg = sbase + (uint32_t)(kt % 3) * kGramStage;
        uint32_t ahi[2][4], alo[2][4];
#pragma unroll
        for (int mt = 0; mt < 2; mt++) {
            const uint32_t co = (uint32_t)(kA * 136 + wm + mt * 16 + mA) * 2;
            ldsm_x4_t(stg +         co, ahi[mt]);
            ldsm_x4_t(stg + 4352u + co, alo[mt]);
        }
#pragma unroll
        for (int ng = 0; ng < 4; ng++) {
            uint32_t bh[4], bl[4];
            const uint32_t co = (uint32_t)(kB * 136 + wn + ng * 16 + nB) * 2;
            ldsm_x4_t(stg + 8704u  + co, bh);
            ldsm_x4_t(stg + 13056u + co, bl);
#pragma unroll
            for (int mt = 0; mt < 2; mt++) {
#pragma unroll
                for (int j = 0; j < 2; j++) {
                    float* c = acc[mt][ng * 2 + j];
                    mma16816(c, ahi[mt], bh[2 * j], bh[2 * j + 1]);
                    mma16816(c, ahi[mt], bl[2 * j], bl[2 * j + 1]);
                    mma16816(c, alo[mt], bh[2 * j], bh[2 * j + 1]);
                }
            }
        }
    }

    const int g = lane >> 2, tg = lane & 3;
    float* P = part + (size_t)(s * 4 + b) * kC * kC;
#pragma unroll
    for (int mt = 0; mt < 2; mt++) {
#pragma unroll
        for (int nt = 0; nt < 8; nt++) {
            const int r   = m0 + wm + mt * 16 + g;
            const int col = n0 + wn + nt * 8 + tg * 2;
            *(float2*)(P + (size_t)r * kC + col) =
                make_float2(acc[mt][nt][0], acc[mt][nt][1]);
            *(float2*)(P + (size_t)(r + 8) * kC + col) =
                make_float2(acc[mt][nt][2], acc[mt][nt][3]);
        }
    }
}

// ---------------------------------------------------------------------------
// Reduce split-K partials with symmetric mirroring -> G as bf16 hi/lo.
// ---------------------------------------------------------------------------
__global__ __launch_bounds__(256) void reduce_g(
    const float* __restrict__ part,
    __nv_bfloat16* __restrict__ Gh, __nv_bfloat16* __restrict__ Gl)
{
    const int i = blockIdx.x * 256 + threadIdx.x;
    const int b = i >> 18;
    const int r = (i >> 9) & 511;
    const int c = i & 511;
    const size_t src = ((r >> 7) <= (c >> 7))
        ? ((size_t)r * kC + c) : ((size_t)c * kC + r);
    float sum = 0.f;
#pragma unroll
    for (int s = 0; s < kSplitK; s++)
        sum += part[(size_t)(s * 4 + b) * kC * kC + src];
    const size_t o = (size_t)b * kC * kC + (size_t)r * kC + c;
    __nv_bfloat16 h = __float2bfloat16_rn(sum);
    Gh[o] = h;
    Gl[o] = __float2bfloat16_rn(sum - __bfloat162float(h));
}

// ---------------------------------------------------------------------------
// bf16x3 tensor GEMM: C = A @ B^T, 128x128 tile, K=512, batched over z.
// outF != nullptr -> fp32 output; else (outH,outL) bf16 hi/lo split output.
// Stage: Ah|Al|Bh|Bl each 128x24 bf16 rows (24576 B); 3 stages.
// ---------------------------------------------------------------------------
static constexpr int kYStage = 4 * 128 * 24 * 2;   // 24576 B
static constexpr int kYSmem  = 3 * kYStage;        // 73728 B

__global__ __launch_bounds__(256, 2) void gemm_tcz(
    const __nv_bfloat16* __restrict__ Ahi, const __nv_bfloat16* __restrict__ Alo,
    size_t strideA,
    const __nv_bfloat16* __restrict__ Bhi, const __nv_bfloat16* __restrict__ Blo,
    size_t strideB,
    const float* __restrict__ bias,
    float* __restrict__ outF,
    __nv_bfloat16* __restrict__ outH, __nv_bfloat16* __restrict__ outL,
    int ldc, size_t strideC)
{
    extern __shared__ __align__(16) char smem[];
    const uint32_t sbase = (uint32_t)__cvta_generic_to_shared(smem);

    const int tid = threadIdx.x, wid = tid >> 5, lane = tid & 31;
    const int n0 = blockIdx.x * 128;
    const int m0 = blockIdx.y * 128;
    const int z  = blockIdx.z;
    const int wm = (wid >> 1) * 32, wn = (wid & 1) * 64;

    const __nv_bfloat16* Ah = Ahi + strideA * z + (size_t)m0 * kC;
    const __nv_bfloat16* Al = Alo + strideA * z + (size_t)m0 * kC;
    const __nv_bfloat16* Bh = Bhi + strideB * z + (size_t)n0 * kC;
    const __nv_bfloat16* Bl = Blo + strideB * z + (size_t)n0 * kC;

    const int lrow = tid >> 1;
    const int lk8  = (tid & 1) * 8;

    auto issue = [&](int kt) {
        const uint32_t stg = sbase + (uint32_t)(kt % 3) * kYStage;
        const uint32_t d = (uint32_t)(lrow * 24 + lk8) * 2;
        const size_t ro = (size_t)lrow * kC + kt * 16 + lk8;
        cp16(stg +          d, Ah + ro);
        cp16(stg + 6144u  + d, Al + ro);
        cp16(stg + 12288u + d, Bh + ro);
        cp16(stg + 18432u + d, Bl + ro);
        cp_commit();
    };

    const int aRow = lane & 15;
    const int aKof = (lane >> 4) * 8;
    const int bRow = (lane & 7) + ((lane >> 4) & 1) * 8;
    const int bKof = ((lane >> 3) & 1) * 8;

    float acc[2][8][4];
#pragma unroll
    for (int mt = 0; mt < 2; mt++)
#pragma unroll
        for (int nt = 0; nt < 8; nt++)
#pragma unroll
            for (int i = 0; i < 4; i++) acc[mt][nt][i] = 0.f;

    const int NK = kC / 16;   // 32
    issue(0); issue(1);

#pragma unroll 1
    for (int kt = 0; kt < NK; kt++) {
        cp_wait<1>();
        __syncthreads();
        if (kt + 2 < NK) issue(kt + 2);
        else             cp_commit();

        const uint32_t stg = sbase + (uint32_t)(kt % 3) * kYStage;
        uint32_t ahi[2][4], alo[2][4];
#pragma unroll
        for (int mt = 0; mt < 2; mt++) {
            const uint32_t co = (uint32_t)((wm + mt * 16 + aRow) * 24 + aKof) * 2;
            ldsm_x4(stg +         co, ahi[mt]);
            ldsm_x4(stg + 6144u + co, alo[mt]);
        }
#pragma unroll
        for (int ng = 0; ng < 4; ng++) {
            uint32_t bh[4], bl[4];
            const uint32_t co = (uint32_t)((wn + ng * 16 + bRow) * 24 + bKof) * 2;
            ldsm_x4(stg + 12288u + co, bh);
            ldsm_x4(stg + 18432u + co, bl);
#pragma unroll
            for (int mt = 0; mt < 2; mt++) {
#pragma unroll
                for (int j = 0; j < 2; j++) {
                    float* c = acc[mt][ng * 2 + j];
                    mma16816(c, ahi[mt], bh[2 * j], bh[2 * j + 1]);
                    mma16816(c, ahi[mt], bl[2 * j], bl[2 * j + 1]);
                    mma16816(c, alo[mt], bh[2 * j], bh[2 * j + 1]);
                }
            }
        }
    }

    const int g = lane >> 2, tg = lane & 3;
#pragma unroll
    for (int mt = 0; mt < 2; mt++) {
#pragma unroll
        for (int nt = 0; nt < 8; nt++) {
            const int r   = m0 + wm + mt * 16 + g;
            const int col = n0 + wn + nt * 8 + tg * 2;
            float v0 = acc[mt][nt][0], v1 = acc[mt][nt][1];
            float v2 = acc[mt][nt][2], v3 = acc[mt][nt][3];
            if (bias) {
                v0 += bias[col]; v1 += bias[col + 1];
                v2 += bias[col]; v3 += bias[col + 1];
            }
            const size_t o0 = strideC * z + (size_t)r * ldc + col;
            const size_t o1 = strideC * z + (size_t)(r + 8) * ldc + col;
            if (outF) {
                *(float2*)(outF + o0) = make_float2(v0, v1);
                *(float2*)(outF + o1) = make_float2(v2, v3);
            } else {
                uint32_t h0 = pack_hi2(v0, v1), h1 = pack_hi2(v2, v3);
                *(uint32_t*)(outH + o0) = h0;
                *(uint32_t*)(outH + o1) = h1;
                *(uint32_t*)(outL + o0) = pack_lo2(v0, v1, h0);
                *(uint32_t*)(outL + o1) = pack_lo2(v2, v3, h1);
            }
        }
    }
}

// ---------------------------------------------------------------------------
// logits_h = SCALE * P1_h @ Wv_h^T (64x64, K=512), row softmax -> attn.
// ---------------------------------------------------------------------------
__global__ __launch_bounds__(256) void logits_softmax(
    const float* __restrict__ P1, const float* __restrict__ Wqkv,
    float* __restrict__ attn)
{
    const int h = blockIdx.x, b = blockIdx.y;
    const float* p1 = P1 + (size_t)b * kC * kC + (size_t)(h * 64) * kC;
    const float* wv = Wqkv + (size_t)(1024 + h * 64) * kC;

    __shared__ float ps[16][68];
    __shared__ float vs[16][68];
    __shared__ float ls[64][68];

    const int tid = threadIdx.x;
    const int ty = tid >> 4, tx = tid & 15;
    const int lr = tid >> 2, lc = (tid & 3) * 4;

    float acc[4][4];
#pragma unroll
    for (int i = 0; i < 4; i++)
#pragma unroll
        for (int j = 0; j < 4; j++) acc[i][j] = 0.f;

    for (int c0 = 0; c0 < kC; c0 += 16) {
        float4 pv = *(const float4*)(p1 + (size_t)lr * kC + c0 + lc);
        float4 vv = *(const float4*)(wv + (size_t)lr * kC + c0 + lc);
        __syncthreads();
        ps[lc+0][lr]=pv.x; ps[lc+1][lr]=pv.y; ps[lc+2][lr]=pv.z; ps[lc+3][lr]=pv.w;
        vs[lc+0][lr]=vv.x; vs[lc+1][lr]=vv.y; vs[lc+2][lr]=vv.z; vs[lc+3][lr]=vv.w;
        __syncthreads();
#pragma unroll
        for (int cc = 0; cc < 16; cc++) {
            float a[4], v[4];
#pragma unroll
            for (int i = 0; i < 4; i++) a[i] = ps[cc][ty * 4 + i];
#pragma unroll
            for (int j = 0; j < 4; j++) v[j] = vs[cc][tx * 4 + j];
#pragma unroll
            for (int i = 0; i < 4; i++)
#pragma unroll
                for (int j = 0; j < 4; j++)
                    acc[i][j] += a[i] * v[j];
        }
    }

    __syncthreads();
#pragma unroll
    for (int i = 0; i < 4; i++)
#pragma unroll
        for (int j = 0; j < 4; j++)
            ls[ty * 4 + i][tx * 4 + j] = acc[i][j];
    __syncthreads();

    const int warp = tid >> 5, lane = tid & 31;
    float* arow_base = attn + (size_t)(b * 8 + h) * 4096;
    for (int r = 0; r < 8; r++) {
        const int d = warp * 8 + r;
        float v1 = kScale * ls[d][lane];
        float v2 = kScale * ls[d][lane + 32];
        float m = fmaxf(v1, v2);
#pragma unroll
        for (int s = 16; s > 0; s >>= 1)
            m = fmaxf(m, __shfl_xor_sync(0xffffffffu, m, s));
        float e1 = expf(v1 - m), e2 = expf(v2 - m);
        float sm = e1 + e2;
#pragma unroll
        for (int s = 16; s > 0; s >>= 1)
            sm += __shfl_xor_sync(0xffffffffu, sm, s);
        float inv = 1.f / sm;
        arow_base[d * 64 + lane]      = e1 * inv;
        arow_base[d * 64 + lane + 32] = e2 * inv;
    }
}

// ---------------------------------------------------------------------------
// Wht_b[c][h*64+d] = sum_e attn_h[d,e] * Wq[h*64+e][c] -> bf16 hi/lo.
// ---------------------------------------------------------------------------
static constexpr int kWhatSmem = (64 * 68 + 64 * 132) * 4;

__global__ __launch_bounds__(256) void what_t(
    const float* __restrict__ attn, const float* __restrict__ Wqkv,
    __nv_bfloat16* __restrict__ whth, __nv_bfloat16* __restrict__ whtl)
{
    extern __shared__ __align__(16) float ws[];
    float (*at)[68]  = (float(*)[68])ws;
    float (*wq)[132] = (float(*)[132])(ws + 64 * 68);

    const int h = blockIdx.x, b = blockIdx.y;
    const float* ag = attn + (size_t)(b * 8 + h) * 4096;
    const float* Wq = Wqkv + (size_t)(h * 64) * kC;
    const size_t obase = (size_t)b * kC * kC;

    const int tid = threadIdx.x;
    for (int i = tid; i < 4096; i += 256)
        at[i >> 6][i & 63] = ag[i];

    const int dG = (tid & 15) * 4;
    const int cB = tid >> 4;

    for (int cb = 0; cb < 4; cb++) {
        __syncthreads();
        for (int i = 0; i < 8; i++) {
            const int f4 = tid + i * 256;
            const int e  = f4 >> 5;
            const int cq = (f4 & 31) * 4;
            *(float4*)&wq[e][cq] =
                *(const float4*)(Wq + (size_t)e * kC + cb * 128 + cq);
        }
        __syncthreads();

        float o[8][4];
#pragma unroll
        for (int i = 0; i < 8; i++)
#pragma unroll
            for (int j = 0; j < 4; j++) o[i][j] = 0.f;

#pragma unroll 4
        for (int e = 0; e < 64; e++) {
            float a[4], w[8];
#pragma unroll
            for (int j = 0; j < 4; j++) a[j] = at[dG + j][e];
#pragma unroll
            for (int i = 0; i < 8; i++) w[i] = wq[e][cB * 8 + i];
#pragma unroll
            for (int i = 0; i < 8; i++)
#pragma unroll
                for (int j = 0; j < 4; j++)
                    o[i][j] += w[i] * a[j];
        }

#pragma unroll
        for (int i = 0; i < 8; i++) {
            const int c = cb * 128 + cB * 8 + i;
            const size_t oo = obase + (size_t)c * kC + h * 64 + dG;
            uint32_t h0 = pack_hi2(o[i][0], o[i][1]);
            uint32_t h1 = pack_hi2(o[i][2], o[i][3]);
            uint32_t l0 = pack_lo2(o[i][0], o[i][1], h0);
            uint32_t l1 = pack_lo2(o[i][2], o[i][3], h1);
            ((uint32_t*)(whth + oo))[0] = h0;
            ((uint32_t*)(whth + oo))[1] = h1;
            ((uint32_t*)(whtl + oo))[0] = l0;
            ((uint32_t*)(whtl + oo))[1] = l1;
        }
    }
}

// ---------------------------------------------------------------------------
extern "C" void kernel_launch(void* const* d_in, const int* in_sizes, int n_in,
                              void* d_out, int out_size)
{
    const float* x     = (const float*)d_in[0];
    const float* Wqkv  = (const float*)d_in[1];
    const float* Wproj = (const float*)d_in[2];
    const float* bproj = (const float*)d_in[3];
    float* out = (float*)d_out;

    __nv_bfloat16 *xh, *xl, *Gh, *Gl, *whth, *whtl, *wth, *wtl,
                  *wkh, *wkl, *wph, *wpl;
    float *gpart, *P1, *attn;
    cudaGetSymbolAddress((void**)&xh,    g_xh);
    cudaGetSymbolAddress((void**)&xl,    g_xl);
    cudaGetSymbolAddress((void**)&gpart, g_gpart);
    cudaGetSymbolAddress((void**)&Gh,    g_Gh);
    cudaGetSymbolAddress((void**)&Gl,    g_Gl);
    cudaGetSymbolAddress((void**)&P1,    g_P1);
    cudaGetSymbolAddress((void**)&attn,  g_attn);
    cudaGetSymbolAddress((void**)&whth,  g_whth);
    cudaGetSymbolAddress((void**)&whtl,  g_whtl);
    cudaGetSymbolAddress((void**)&wth,   g_wth);
    cudaGetSymbolAddress((void**)&wtl,   g_wtl);
    cudaGetSymbolAddress((void**)&wkh,   g_wkh);
    cudaGetSymbolAddress((void**)&wkl,   g_wkl);
    cudaGetSymbolAddress((void**)&wph,   g_wph);
    cudaGetSymbolAddress((void**)&wpl,   g_wpl);

    cudaFuncSetAttribute(gemm_gram,
        cudaFuncAttributeMaxDynamicSharedMemorySize, kGramSmem);
    cudaFuncSetAttribute(what_t,
        cudaFuncAttributeMaxDynamicSharedMemorySize, kWhatSmem);
    cudaFuncSetAttribute(gemm_tcz,
        cudaFuncAttributeMaxDynamicSharedMemorySize, kYSmem);

    const size_t cc = (size_t)kC * kC;

    // 1) splits: X, Wk (Wqkv rows 512..1024), Wproj
    split_f32<<<(kM * kC / 4 + 255) / 256, 256>>>(x, xh, xl, kM * kC / 4);
    split_f32<<<((int)cc / 4 + 255) / 256, 256>>>(Wqkv + cc, wkh, wkl, (int)cc / 4);
    split_f32<<<((int)cc / 4 + 255) / 256, 256>>>(Wproj, wph, wpl, (int)cc / 4);

    // 2) Gram partials (split-K 8 -> grid 320, 2 CTA/SM)
    gemm_gram<<<dim3(10, 4 * kSplitK), 256, kGramSmem>>>(xh, xl, gpart);

    // 3) reduce + mirror -> G (bf16 hi/lo)
    reduce_g<<<(4 * (int)cc) / 256, 256>>>(gpart, Gh, Gl);

    // 4) P1_b = Wk @ G_b  (G symmetric)  [tensor, fp32 out]
    gemm_tcz<<<dim3(4, 4, 4), 256, kYSmem>>>(
        wkh, wkl, 0, Gh, Gl, cc, nullptr, P1, nullptr, nullptr, kC, cc);

    // 5) logits + softmax -> attn
    logits_softmax<<<dim3(8, 4), 256>>>(P1, Wqkv, attn);

    // 6) Wht_b = (attn_h @ Wq_h)^T  -> bf16 hi/lo
    what_t<<<dim3(8, 4), 256, kWhatSmem>>>(attn, Wqkv, whth, whtl);

    // 7) Wt_b = Wproj @ Wht_b^T  [tensor, bf16 hi/lo out]
    gemm_tcz<<<dim3(4, 4, 4), 256, kYSmem>>>(
        wph, wpl, 0, whth, whtl, cc, nullptr, nullptr, wth, wtl, kC, cc);

    // 8) y = X @ Wt_b^T + bproj  [tensor]
    gemm_tcz<<<dim3(4, kTok / 128, 4), 256, kYSmem>>>(
        xh, xl, (size_t)kTok * kC, wth, wtl, cc, bproj,
        out, nullptr, nullptr, kC, (size_t)kTok * kC);
}

// round 10
// speedup vs baseline: 2.1039x; 1.0346x over previous
#include <cuda_runtime.h>
#include <cuda_bf16.h>
#include <cstdint>
#include <cstddef>

// ---------------------------------------------------------------------------
// ChannelAttention via Gram factorization (all heavy GEMMs on tensor cores):
//   G_b   = X_b^T X_b          (bf16x3 mma, ldmatrix.trans, split-K 8)
//   P1_b  = Wk @ G_b           (bf16x3 mma)
//   logit = softmax(SCALE * P1_h @ Wv_h^T)   (FFMA, tiny)
//   Wht_b = (attn_h @ Wq_h)^T                (FFMA, tiny, emits bf16 hi/lo)
//   Wt_b  = Wproj @ Wht_b^T                  (bf16x3 mma, emits bf16 hi/lo)
//   y     = X @ Wt_b^T + bproj               (bf16x3 mma)
// Round 10: 64x64 warp tiles (4 warps / 128 threads per CTA) to cut smem
// crossbar traffic per MMA (was the measured 50%-tensor ceiling).
// ---------------------------------------------------------------------------

static constexpr int   kTok   = 8192;
static constexpr int   kC     = 512;
static constexpr int   kM     = 4 * kTok;       // 32768
static constexpr float kScale = 0.125f;
static constexpr int   kSplitK = 8;             // gram split-K
static constexpr int   kKS     = kTok / kSplitK;  // 1024 tokens per split

// Scratch (device globals; all read locations rewritten each launch)
__device__ __nv_bfloat16 g_xh [(size_t)kM * kC];
__device__ __nv_bfloat16 g_xl [(size_t)kM * kC];
__device__ float g_gpart[(size_t)kSplitK * 4 * kC * kC];
__device__ __nv_bfloat16 g_Gh [(size_t)4 * kC * kC];
__device__ __nv_bfloat16 g_Gl [(size_t)4 * kC * kC];
__device__ float g_P1   [(size_t)4 * kC * kC];
__device__ float g_attn [(size_t)32 * 64 * 64];
__device__ __nv_bfloat16 g_whth[(size_t)4 * kC * kC];
__device__ __nv_bfloat16 g_whtl[(size_t)4 * kC * kC];
__device__ __nv_bfloat16 g_wth[(size_t)4 * kC * kC];
__device__ __nv_bfloat16 g_wtl[(size_t)4 * kC * kC];
__device__ __nv_bfloat16 g_wkh[(size_t)kC * kC];
__device__ __nv_bfloat16 g_wkl[(size_t)kC * kC];
__device__ __nv_bfloat16 g_wph[(size_t)kC * kC];
__device__ __nv_bfloat16 g_wpl[(size_t)kC * kC];

// ---------------------------------------------------------------------------
// primitives
// ---------------------------------------------------------------------------
__device__ __forceinline__ void ldsm_x4(uint32_t addr, uint32_t* r)
{
    asm volatile("ldmatrix.sync.aligned.m8n8.x4.shared.b16 {%0,%1,%2,%3}, [%4];\n"
                 : "=r"(r[0]), "=r"(r[1]), "=r"(r[2]), "=r"(r[3]) : "r"(addr));
}
__device__ __forceinline__ void ldsm_x4_t(uint32_t addr, uint32_t* r)
{
    asm volatile("ldmatrix.sync.aligned.m8n8.x4.trans.shared.b16 {%0,%1,%2,%3}, [%4];\n"
                 : "=r"(r[0]), "=r"(r[1]), "=r"(r[2]), "=r"(r[3]) : "r"(addr));
}
__device__ __forceinline__ void mma16816(float* c, const uint32_t* a,
                                         uint32_t b0, uint32_t b1)
{
    asm volatile(
        "mma.sync.aligned.m16n8k16.row.col.f32.bf16.bf16.f32 "
        "{%0,%1,%2,%3}, {%4,%5,%6,%7}, {%8,%9}, {%0,%1,%2,%3};\n"
        : "+f"(c[0]), "+f"(c[1]), "+f"(c[2]), "+f"(c[3])
        : "r"(a[0]), "r"(a[1]), "r"(a[2]), "r"(a[3]), "r"(b0), "r"(b1));
}
__device__ __forceinline__ void cp16(uint32_t dst, const void* src)
{
    asm volatile("cp.async.cg.shared.global [%0], [%1], 16;\n" :: "r"(dst), "l"(src));
}
__device__ __forceinline__ void cp_commit()
{
    asm volatile("cp.async.commit_group;\n");
}
template <int N> __device__ __forceinline__ void cp_wait()
{
    asm volatile("cp.async.wait_group %0;\n" :: "n"(N));
}
__device__ __forceinline__ uint32_t pack_hi2(float a, float b)
{
    __nv_bfloat162 p;
    p.x = __float2bfloat16_rn(a);
    p.y = __float2bfloat16_rn(b);
    return *reinterpret_cast<uint32_t*>(&p);
}
__device__ __forceinline__ uint32_t pack_lo2(float a, float b, uint32_t hi)
{
    __nv_bfloat162 h = *reinterpret_cast<__nv_bfloat162*>(&hi);
    __nv_bfloat162 p;
    p.x = __float2bfloat16_rn(a - __bfloat162float(h.x));
    p.y = __float2bfloat16_rn(b - __bfloat162float(h.y));
    return *reinterpret_cast<uint32_t*>(&p);
}

// ---------------------------------------------------------------------------
// fp32 -> (hi, lo) bf16 split
// ---------------------------------------------------------------------------
__global__ __launch_bounds__(256) void split_f32(
    const float* __restrict__ src,
    __nv_bfloat16* __restrict__ hi, __nv_bfloat16* __restrict__ lo, int n4)
{
    int i = blockIdx.x * blockDim.x + threadIdx.x;
    if (i >= n4) return;
    float4 f = ((const float4*)src)[i];
    float a[4] = {f.x, f.y, f.z, f.w};
    __nv_bfloat16 h[4], l[4];
#pragma unroll
    for (int j = 0; j < 4; j++) {
        h[j] = __float2bfloat16_rn(a[j]);
        l[j] = __float2bfloat16_rn(a[j] - __bfloat162float(h[j]));
    }
    ((uint2*)hi)[i] = *(uint2*)h;
    ((uint2*)lo)[i] = *(uint2*)l;
}

// ---------------------------------------------------------------------------
// Gram partials (bf16x3, ldmatrix.trans), split-K 8.
// 128 threads, 4 warps of 64x64. CTA tile 128x128 (upper-tri block pairs).
// Stage: Ah | Al | Bh | Bl, each 16 rows x 136 bf16 (272B rows) = 17408 B.
// ---------------------------------------------------------------------------
static constexpr int kGramStage = 4 * 16 * 136 * 2;   // 17408 B
static constexpr int kGramSmem  = 3 * kGramStage;     // 52224 B

__global__ __launch_bounds__(128, 2) void gemm_gram(
    const __nv_bfloat16* __restrict__ Xhi,
    const __nv_bfloat16* __restrict__ Xlo,
    float* __restrict__ part)
{
    extern __shared__ __align__(16) char smem[];
    const uint32_t sbase = (uint32_t)__cvta_generic_to_shared(smem);

    int p = blockIdx.x, mb = 0;
    while (p >= 4 - mb) { p -= 4 - mb; mb++; }
    const int m0 = mb * 128, n0 = (mb + p) * 128;
    const int bz = blockIdx.y;           // b*kSplitK + s
    const int b = bz >> 3, s = bz & 7;
    const size_t tokBase = (size_t)b * kTok + (size_t)s * kKS;

    const int tid = threadIdx.x, wid = tid >> 5, lane = tid & 31;
    const int wm = (wid >> 1) * 64, wn = (wid & 1) * 64;

    // loader: 128 threads cover 2 of 256 16B-chunks per array each
    const int c0row = tid >> 3;            // chunk tid:   row 0..15
    const int c0ch  = (tid & 7) * 16;      // bf16 col 0..112 (16 per chunk)
    const int c1ch  = c0ch + 8;            // second chunk: +8 bf16 (16B)
    // chunks c0 = (row, col c0ch), c1 = (row, col c1ch)? No: cover 16 cols/row
    // per row there are 16 chunks of 8 bf16. tid&7 covers 8; pairs (2k,2k+1).

    auto issue = [&](int kt) {
        const uint32_t stg = sbase + (uint32_t)(kt % 3) * kGramStage;
        const int row = c0row;
        const size_t ro = (tokBase + (size_t)kt * 16 + row) * kC;
        const int chA = (tid & 7) * 16;        // first 8-bf16 chunk col
        const int chB = chA + 8;               // second
        const uint32_t dA = (uint32_t)(row * 136 + chA) * 2;
        const uint32_t dB = (uint32_t)(row * 136 + chB) * 2;
        cp16(stg +          dA, Xhi + ro + m0 + chA);
        cp16(stg +          dB, Xhi + ro + m0 + chB);
        cp16(stg + 4352u  + dA, Xlo + ro + m0 + chA);
        cp16(stg + 4352u  + dB, Xlo + ro + m0 + chB);
        cp16(stg + 8704u  + dA, Xhi + ro + n0 + chA);
        cp16(stg + 8704u  + dB, Xhi + ro + n0 + chB);
        cp16(stg + 13056u + dA, Xlo + ro + n0 + chA);
        cp16(stg + 13056u + dB, Xlo + ro + n0 + chB);
        cp_commit();
    };

    // trans fragment lane mapping
    const int kA = (lane & 7) + ((lane >> 4) & 1) * 8;
    const int mA = ((lane >> 3) & 1) * 8;
    const int kB = (lane & 7) + ((lane >> 3) & 1) * 8;
    const int nB = ((lane >> 4) & 1) * 8;

    float acc[4][8][4];
#pragma unroll
    for (int mt = 0; mt < 4; mt++)
#pragma unroll
        for (int nt = 0; nt < 8; nt++)
#pragma unroll
            for (int i = 0; i < 4; i++) acc[mt][nt][i] = 0.f;

    const int NK = kKS / 16;   // 64
    issue(0); issue(1);

#pragma unroll 1
    for (int kt = 0; kt < NK; kt++) {
        cp_wait<1>();
        __syncthreads();
        if (kt + 2 < NK) issue(kt + 2);
        else             cp_commit();

        const uint32_t stg = sbase + (uint32_t)(kt % 3) * kGramStage;
        uint32_t ahi[4][4], alo[4][4];
#pragma unroll
        for (int mt = 0; mt < 4; mt++) {
            const uint32_t co = (uint32_t)(kA * 136 + wm + mt * 16 + mA) * 2;
            ldsm_x4_t(stg +         co, ahi[mt]);
            ldsm_x4_t(stg + 4352u + co, alo[mt]);
        }
#pragma unroll
        for (int ng = 0; ng < 4; ng++) {
            uint32_t bh[4], bl[4];
            const uint32_t co = (uint32_t)(kB * 136 + wn + ng * 16 + nB) * 2;
            ldsm_x4_t(stg + 8704u  + co, bh);
            ldsm_x4_t(stg + 13056u + co, bl);
#pragma unroll
            for (int mt = 0; mt < 4; mt++) {
#pragma unroll
                for (int j = 0; j < 2; j++) {
                    float* c = acc[mt][ng * 2 + j];
                    mma16816(c, ahi[mt], bh[2 * j], bh[2 * j + 1]);
                    mma16816(c, ahi[mt], bl[2 * j], bl[2 * j + 1]);
                    mma16816(c, alo[mt], bh[2 * j], bh[2 * j + 1]);
                }
            }
        }
    }

    const int g = lane >> 2, tg = lane & 3;
    float* P = part + (size_t)(s * 4 + b) * kC * kC;
#pragma unroll
    for (int mt = 0; mt < 4; mt++) {
#pragma unroll
        for (int nt = 0; nt < 8; nt++) {
            const int r   = m0 + wm + mt * 16 + g;
            const int col = n0 + wn + nt * 8 + tg * 2;
            *(float2*)(P + (size_t)r * kC + col) =
                make_float2(acc[mt][nt][0], acc[mt][nt][1]);
            *(float2*)(P + (size_t)(r + 8) * kC + col) =
                make_float2(acc[mt][nt][2], acc[mt][nt][3]);
        }
    }
}

// ---------------------------------------------------------------------------
// Reduce split-K partials with symmetric mirroring -> G as bf16 hi/lo.
// ---------------------------------------------------------------------------
__global__ __launch_bounds__(256) void reduce_g(
    const float* __restrict__ part,
    __nv_bfloat16* __restrict__ Gh, __nv_bfloat16* __restrict__ Gl)
{
    const int i = blockIdx.x * 256 + threadIdx.x;
    const int b = i >> 18;
    const int r = (i >> 9) & 511;
    const int c = i & 511;
    const size_t src = ((r >> 7) <= (c >> 7))
        ? ((size_t)r * kC + c) : ((size_t)c * kC + r);
    float sum = 0.f;
#pragma unroll
    for (int s = 0; s < kSplitK; s++)
        sum += part[(size_t)(s * 4 + b) * kC * kC + src];
    const size_t o = (size_t)b * kC * kC + (size_t)r * kC + c;
    __nv_bfloat16 h = __float2bfloat16_rn(sum);
    Gh[o] = h;
    Gl[o] = __float2bfloat16_rn(sum - __bfloat162float(h));
}

// ---------------------------------------------------------------------------
// bf16x3 tensor GEMM: C = A @ B^T, CTA 128x128 (4 warps of 64x64), K=512,
// batched over z. outF -> fp32 out; else (outH,outL) bf16 hi/lo out.
// Stage: Ah|Al|Bh|Bl each 128x24 bf16 rows (24576 B); 3 stages.
// ---------------------------------------------------------------------------
static constexpr int kYStage = 4 * 128 * 24 * 2;   // 24576 B
static constexpr int kYSmem  = 3 * kYStage;        // 73728 B

__global__ __launch_bounds__(128, 2) void gemm_tcz(
    const __nv_bfloat16* __restrict__ Ahi, const __nv_bfloat16* __restrict__ Alo,
    size_t strideA,
    const __nv_bfloat16* __restrict__ Bhi, const __nv_bfloat16* __restrict__ Blo,
    size_t strideB,
    const float* __restrict__ bias,
    float* __restrict__ outF,
    __nv_bfloat16* __restrict__ outH, __nv_bfloat16* __restrict__ outL,
    int ldc, size_t strideC)
{
    extern __shared__ __align__(16) char smem[];
    const uint32_t sbase = (uint32_t)__cvta_generic_to_shared(smem);

    const int tid = threadIdx.x, wid = tid >> 5, lane = tid & 31;
    const int n0 = blockIdx.x * 128;
    const int m0 = blockIdx.y * 128;
    const int z  = blockIdx.z;
    const int wm = (wid >> 1) * 64, wn = (wid & 1) * 64;

    const __nv_bfloat16* Ah = Ahi + strideA * z + (size_t)m0 * kC;
    const __nv_bfloat16* Al = Alo + strideA * z + (size_t)m0 * kC;
    const __nv_bfloat16* Bh = Bhi + strideB * z + (size_t)n0 * kC;
    const __nv_bfloat16* Bl = Blo + strideB * z + (size_t)n0 * kC;

    // loader: 128 threads, rows lrow and lrow+64, 16B chunk each
    const int lrow = tid >> 1;          // 0..63
    const int lk8  = (tid & 1) * 8;     // 0 or 8

    auto issue = [&](int kt) {
        const uint32_t stg = sbase + (uint32_t)(kt % 3) * kYStage;
        const int kk = kt * 16 + lk8;
#pragma unroll
        for (int half = 0; half < 2; half++) {
            const int row = lrow + half * 64;
            const uint32_t d = (uint32_t)(row * 24 + lk8) * 2;
            const size_t ro = (size_t)row * kC + kk;
            cp16(stg +          d, Ah + ro);
            cp16(stg + 6144u  + d, Al + ro);
            cp16(stg + 12288u + d, Bh + ro);
            cp16(stg + 18432u + d, Bl + ro);
        }
        cp_commit();
    };

    const int aRow = lane & 15;
    const int aKof = (lane >> 4) * 8;
    const int bRow = (lane & 7) + ((lane >> 4) & 1) * 8;
    const int bKof = ((lane >> 3) & 1) * 8;

    float acc[4][8][4];
#pragma unroll
    for (int mt = 0; mt < 4; mt++)
#pragma unroll
        for (int nt = 0; nt < 8; nt++)
#pragma unroll
            for (int i = 0; i < 4; i++) acc[mt][nt][i] = 0.f;

    const int NK = kC / 16;   // 32
    issue(0); issue(1);

#pragma unroll 1
    for (int kt = 0; kt < NK; kt++) {
        cp_wait<1>();
        __syncthreads();
        if (kt + 2 < NK) issue(kt + 2);
        else             cp_commit();

        const uint32_t stg = sbase + (uint32_t)(kt % 3) * kYStage;
        uint32_t ahi[4][4], alo[4][4];
#pragma unroll
        for (int mt = 0; mt < 4; mt++) {
            const uint32_t co = (uint32_t)((wm + mt * 16 + aRow) * 24 + aKof) * 2;
            ldsm_x4(stg +         co, ahi[mt]);
            ldsm_x4(stg + 6144u + co, alo[mt]);
        }
#pragma unroll
        for (int ng = 0; ng < 4; ng++) {
            uint32_t bh[4], bl[4];
            const uint32_t co = (uint32_t)((wn + ng * 16 + bRow) * 24 + bKof) * 2;
            ldsm_x4(stg + 12288u + co, bh);
            ldsm_x4(stg + 18432u + co, bl);
#pragma unroll
            for (int mt = 0; mt < 4; mt++) {
#pragma unroll
                for (int j = 0; j < 2; j++) {
                    float* c = acc[mt][ng * 2 + j];
                    mma16816(c, ahi[mt], bh[2 * j], bh[2 * j + 1]);
                    mma16816(c, ahi[mt], bl[2 * j], bl[2 * j + 1]);
                    mma16816(c, alo[mt], bh[2 * j], bh[2 * j + 1]);
                }
            }
        }
    }

    const int g = lane >> 2, tg = lane & 3;
#pragma unroll
    for (int mt = 0; mt < 4; mt++) {
#pragma unroll
        for (int nt = 0; nt < 8; nt++) {
            const int r   = m0 + wm + mt * 16 + g;
            const int col = n0 + wn + nt * 8 + tg * 2;
            float v0 = acc[mt][nt][0], v1 = acc[mt][nt][1];
            float v2 = acc[mt][nt][2], v3 = acc[mt][nt][3];
            if (bias) {
                v0 += bias[col]; v1 += bias[col + 1];
                v2 += bias[col]; v3 += bias[col + 1];
            }
            const size_t o0 = strideC * z + (size_t)r * ldc + col;
            const size_t o1 = strideC * z + (size_t)(r + 8) * ldc + col;
            if (outF) {
                *(float2*)(outF + o0) = make_float2(v0, v1);
                *(float2*)(outF + o1) = make_float2(v2, v3);
            } else {
                uint32_t h0 = pack_hi2(v0, v1), h1 = pack_hi2(v2, v3);
                *(uint32_t*)(outH + o0) = h0;
                *(uint32_t*)(outH + o1) = h1;
                *(uint32_t*)(outL + o0) = pack_lo2(v0, v1, h0);
                *(uint32_t*)(outL + o1) = pack_lo2(v2, v3, h1);
            }
        }
    }
}

// ---------------------------------------------------------------------------
// logits_h = SCALE * P1_h @ Wv_h^T (64x64, K=512), row softmax -> attn.
// ---------------------------------------------------------------------------
__global__ __launch_bounds__(256) void logits_softmax(
    const float* __restrict__ P1, const float* __restrict__ Wqkv,
    float* __restrict__ attn)
{
    const int h = blockIdx.x, b = blockIdx.y;
    const float* p1 = P1 + (size_t)b * kC * kC + (size_t)(h * 64) * kC;
    const float* wv = Wqkv + (size_t)(1024 + h * 64) * kC;

    __shared__ float ps[16][68];
    __shared__ float vs[16][68];
    __shared__ float ls[64][68];

    const int tid = threadIdx.x;
    const int ty = tid >> 4, tx = tid & 15;
    const int lr = tid >> 2, lc = (tid & 3) * 4;

    float acc[4][4];
#pragma unroll
    for (int i = 0; i < 4; i++)
#pragma unroll
        for (int j = 0; j < 4; j++) acc[i][j] = 0.f;

    for (int c0 = 0; c0 < kC; c0 += 16) {
        float4 pv = *(const float4*)(p1 + (size_t)lr * kC + c0 + lc);
        float4 vv = *(const float4*)(wv + (size_t)lr * kC + c0 + lc);
        __syncthreads();
        ps[lc+0][lr]=pv.x; ps[lc+1][lr]=pv.y; ps[lc+2][lr]=pv.z; ps[lc+3][lr]=pv.w;
        vs[lc+0][lr]=vv.x; vs[lc+1][lr]=vv.y; vs[lc+2][lr]=vv.z; vs[lc+3][lr]=vv.w;
        __syncthreads();
#pragma unroll
        for (int cc = 0; cc < 16; cc++) {
            float a[4], v[4];
#pragma unroll
            for (int i = 0; i < 4; i++) a[i] = ps[cc][ty * 4 + i];
#pragma unroll
            for (int j = 0; j < 4; j++) v[j] = vs[cc][tx * 4 + j];
#pragma unroll
            for (int i = 0; i < 4; i++)
#pragma unroll
                for (int j = 0; j < 4; j++)
                    acc[i][j] += a[i] * v[j];
        }
    }

    __syncthreads();
#pragma unroll
    for (int i = 0; i < 4; i++)
#pragma unroll
        for (int j = 0; j < 4; j++)
            ls[ty * 4 + i][tx * 4 + j] = acc[i][j];
    __syncthreads();

    const int warp = tid >> 5, lane = tid & 31;
    float* arow_base = attn + (size_t)(b * 8 + h) * 4096;
    for (int r = 0; r < 8; r++) {
        const int d = warp * 8 + r;
        float v1 = kScale * ls[d][lane];
        float v2 = kScale * ls[d][lane + 32];
        float m = fmaxf(v1, v2);
#pragma unroll
        for (int s = 16; s > 0; s >>= 1)
            m = fmaxf(m, __shfl_xor_sync(0xffffffffu, m, s));
        float e1 = expf(v1 - m), e2 = expf(v2 - m);
        float sm = e1 + e2;
#pragma unroll
        for (int s = 16; s > 0; s >>= 1)
            sm += __shfl_xor_sync(0xffffffffu, sm, s);
        float inv = 1.f / sm;
        arow_base[d * 64 + lane]      = e1 * inv;
        arow_base[d * 64 + lane + 32] = e2 * inv;
    }
}

// ---------------------------------------------------------------------------
// Wht_b[c][h*64+d] = sum_e attn_h[d,e] * Wq[h*64+e][c] -> bf16 hi/lo.
// ---------------------------------------------------------------------------
static constexpr int kWhatSmem = (64 * 68 + 64 * 132) * 4;

__global__ __launch_bounds__(256) void what_t(
    const float* __restrict__ attn, const float* __restrict__ Wqkv,
    __nv_bfloat16* __restrict__ whth, __nv_bfloat16* __restrict__ whtl)
{
    extern __shared__ __align__(16) float ws[];
    float (*at)[68]  = (float(*)[68])ws;
    float (*wq)[132] = (float(*)[132])(ws + 64 * 68);

    const int h = blockIdx.x, b = blockIdx.y;
    const float* ag = attn + (size_t)(b * 8 + h) * 4096;
    const float* Wq = Wqkv + (size_t)(h * 64) * kC;
    const size_t obase = (size_t)b * kC * kC;

    const int tid = threadIdx.x;
    for (int i = tid; i < 4096; i += 256)
        at[i >> 6][i & 63] = ag[i];

    const int dG = (tid & 15) * 4;
    const int cB = tid >> 4;

    for (int cb = 0; cb < 4; cb++) {
        __syncthreads();
        for (int i = 0; i < 8; i++) {
            const int f4 = tid + i * 256;
            const int e  = f4 >> 5;
            const int cq = (f4 & 31) * 4;
            *(float4*)&wq[e][cq] =
                *(const float4*)(Wq + (size_t)e * kC + cb * 128 + cq);
        }
        __syncthreads();

        float o[8][4];
#pragma unroll
        for (int i = 0; i < 8; i++)
#pragma unroll
            for (int j = 0; j < 4; j++) o[i][j] = 0.f;

#pragma unroll 4
        for (int e = 0; e < 64; e++) {
            float a[4], w[8];
#pragma unroll
            for (int j = 0; j < 4; j++) a[j] = at[dG + j][e];
#pragma unroll
            for (int i = 0; i < 8; i++) w[i] = wq[e][cB * 8 + i];
#pragma unroll
            for (int i = 0; i < 8; i++)
#pragma unroll
                for (int j = 0; j < 4; j++)
                    o[i][j] += w[i] * a[j];
        }

#pragma unroll
        for (int i = 0; i < 8; i++) {
            const int c = cb * 128 + cB * 8 + i;
            const size_t oo = obase + (size_t)c * kC + h * 64 + dG;
            uint32_t h0 = pack_hi2(o[i][0], o[i][1]);
            uint32_t h1 = pack_hi2(o[i][2], o[i][3]);
            uint32_t l0 = pack_lo2(o[i][0], o[i][1], h0);
            uint32_t l1 = pack_lo2(o[i][2], o[i][3], h1);
            ((uint32_t*)(whth + oo))[0] = h0;
            ((uint32_t*)(whth + oo))[1] = h1;
            ((uint32_t*)(whtl + oo))[0] = l0;
            ((uint32_t*)(whtl + oo))[1] = l1;
        }
    }
}

// ---------------------------------------------------------------------------
extern "C" void kernel_launch(void* const* d_in, const int* in_sizes, int n_in,
                              void* d_out, int out_size)
{
    const float* x     = (const float*)d_in[0];
    const float* Wqkv  = (const float*)d_in[1];
    const float* Wproj = (const float*)d_in[2];
    const float* bproj = (const float*)d_in[3];
    float* out = (float*)d_out;

    __nv_bfloat16 *xh, *xl, *Gh, *Gl, *whth, *whtl, *wth, *wtl,
                  *wkh, *wkl, *wph, *wpl;
    float *gpart, *P1, *attn;
    cudaGetSymbolAddress((void**)&xh,    g_xh);
    cudaGetSymbolAddress((void**)&xl,    g_xl);
    cudaGetSymbolAddress((void**)&gpart, g_gpart);
    cudaGetSymbolAddress((void**)&Gh,    g_Gh);
    cudaGetSymbolAddress((void**)&Gl,    g_Gl);
    cudaGetSymbolAddress((void**)&P1,    g_P1);
    cudaGetSymbolAddress((void**)&attn,  g_attn);
    cudaGetSymbolAddress((void**)&whth,  g_whth);
    cudaGetSymbolAddress((void**)&whtl,  g_whtl);
    cudaGetSymbolAddress((void**)&wth,   g_wth);
    cudaGetSymbolAddress((void**)&wtl,   g_wtl);
    cudaGetSymbolAddress((void**)&wkh,   g_wkh);
    cudaGetSymbolAddress((void**)&wkl,   g_wkl);
    cudaGetSymbolAddress((void**)&wph,   g_wph);
    cudaGetSymbolAddress((void**)&wpl,   g_wpl);

    cudaFuncSetAttribute(gemm_gram,
        cudaFuncAttributeMaxDynamicSharedMemorySize, kGramSmem);
    cudaFuncSetAttribute(what_t,
        cudaFuncAttributeMaxDynamicSharedMemorySize, kWhatSmem);
    cudaFuncSetAttribute(gemm_tcz,
        cudaFuncAttributeMaxDynamicSharedMemorySize, kYSmem);

    const size_t cc = (size_t)kC * kC;

    // 1) splits: X, Wk (Wqkv rows 512..1024), Wproj
    split_f32<<<(kM * kC / 4 + 255) / 256, 256>>>(x, xh, xl, kM * kC / 4);
    split_f32<<<((int)cc / 4 + 255) / 256, 256>>>(Wqkv + cc, wkh, wkl, (int)cc / 4);
    split_f32<<<((int)cc / 4 + 255) / 256, 256>>>(Wproj, wph, wpl, (int)cc / 4);

    // 2) Gram partials (split-K 8, 128-thread CTAs)
    gemm_gram<<<dim3(10, 4 * kSplitK), 128, kGramSmem>>>(xh, xl, gpart);

    // 3) reduce + mirror -> G (bf16 hi/lo)
    reduce_g<<<(4 * (int)cc) / 256, 256>>>(gpart, Gh, Gl);

    // 4) P1_b = Wk @ G_b  (G symmetric)  [tensor, fp32 out]
    gemm_tcz<<<dim3(4, 4, 4), 128, kYSmem>>>(
        wkh, wkl, 0, Gh, Gl, cc, nullptr, P1, nullptr, nullptr, kC, cc);

    // 5) logits + softmax -> attn
    logits_softmax<<<dim3(8, 4), 256>>>(P1, Wqkv, attn);

    // 6) Wht_b = (attn_h @ Wq_h)^T  -> bf16 hi/lo
    what_t<<<dim3(8, 4), 256, kWhatSmem>>>(attn, Wqkv, whth, whtl);

    // 7) Wt_b = Wproj @ Wht_b^T  [tensor, bf16 hi/lo out]
    gemm_tcz<<<dim3(4, 4, 4), 128, kYSmem>>>(
        wph, wpl, 0, whth, whtl, cc, nullptr, nullptr, wth, wtl, kC, cc);

    // 8) y = X @ Wt_b^T + bproj  [tensor]
    gemm_tcz<<<dim3(4, kTok / 128, 4), 128, kYSmem>>>(
        xh, xl, (size_t)kTok * kC, wth, wtl, cc, bproj,
        out, nullptr, nullptr, kC, (size_t)kTok * kC);
}